// round 10
// baseline (speedup 1.0000x reference)
#include <cuda_runtime.h>
#include <math.h>

// Problem dims
#define Vv 32000
#define Ee 512
#define Hh 512
#define Bb 16
#define Tt 128
#define Ss 512

constexpr int BT   = Bb * Tt;          // 2048
constexpr int G4H  = 4 * Hh;           // 2048
constexpr int KIN  = Ee + Hh;          // 1024
constexpr int AIN  = 2 * Hh + Ee;      // 1536
constexpr long OUT0 = (long)BT * Vv;
constexpr long OUT1 = (long)BT * AIN;
constexpr long OUT2 = BT;
constexpr long BSH  = (long)Bb * Ss * Hh;

// ---------------- scratch (device globals) --------------------------------
__device__ float g_lstm_in[BT * KIN];
__device__ float g_Gx[BT * G4H];
__device__ float g_WihT[KIN * G4H];       // W_ih transposed [KIN][4H]
__device__ float g_bsum[G4H];
__device__ float g_hbuf[2][Bb * Hh];
__device__ float g_cbuf[Bb * Hh];
__device__ float g_lohtb[BT * 1024];      // [ lstm_out | h_t_bar ]
__device__ float g_attn_in[BT * AIN];
__device__ float g_att[BT * Ss];
__device__ float g_outpre[BT * Hh];
__device__ int   g_bar;                   // persistent-LSTM grid barrier

// ---------------- fused prep kernel ----------------------------------------
__global__ void k_prep(const int* __restrict__ x,
                       const float* __restrict__ h0,
                       const float* __restrict__ c0,
                       const float* __restrict__ emb,
                       const float* __restrict__ b_ih,
                       const float* __restrict__ b_hh,
                       float* __restrict__ out, int wo, int wt) {
    int i = blockIdx.x * 256 + threadIdx.x;
    if (i == 0) g_bar = 0;
    if (i < G4H) g_bsum[i] = b_ih[i] + b_hh[i];
    if (i < Bb * Hh) { g_hbuf[0][i] = h0[i]; g_cbuf[i] = c0[i]; }
    if (i < BT && wt) out[OUT0 + OUT1 + i] = (float)((Ss / Tt) * (i % Tt));
    if (i >= BT * KIN) return;
    int bt = i / KIN, c = i % KIN;
    int b = bt / Tt;
    float v;
    if (c < Hh) v = h0[b * Hh + c] + c0[b * Hh + c];
    else        v = emb[(long)x[bt] * Ee + (c - Hh)];
    g_lstm_in[i] = v;
    long ao = (long)bt * AIN + Hh + c;     // attention_input cols 512..1535
    g_attn_in[ao] = v;
    if (wo) out[OUT0 + ao] = v;
}

// tiled transpose: W_ih [4H][KIN] -> g_WihT [KIN][4H]
__global__ void k_transpose_wih(const float* __restrict__ W) {
    __shared__ float tile[32][33];
    int bx = blockIdx.x * 32, by = blockIdx.y * 32;
    int x = bx + threadIdx.x;
    #pragma unroll
    for (int i = 0; i < 32; i += 8)
        tile[threadIdx.y + i][threadIdx.x] = W[(long)(by + threadIdx.y + i) * KIN + x];
    __syncthreads();
    int xo = by + threadIdx.x;
    #pragma unroll
    for (int i = 0; i < 32; i += 8)
        g_WihT[(long)(bx + threadIdx.y + i) * G4H + xo] = tile[threadIdx.x][threadIdx.y + i];
}

// ---------------- TF32 helpers --------------------------------------------
__device__ __forceinline__ unsigned f2tf(float f) {
    unsigned u;
    asm("cvt.rna.tf32.f32 %0, %1;" : "=r"(u) : "f"(f));
    return u;
}
#define TFPAD 136           // 136 % 32 == 8 -> conflict-free fragment reads
#define BWPAD 264

#define MMA_TF32(ACC, AF, B0, B1)                                              \
    asm volatile(                                                              \
        "mma.sync.aligned.m16n8k8.row.col.f32.tf32.tf32.f32 "                  \
        "{%0,%1,%2,%3}, {%4,%5,%6,%7}, {%8,%9}, {%0,%1,%2,%3};"                \
        : "+f"((ACC)[0]), "+f"((ACC)[1]), "+f"((ACC)[2]), "+f"((ACC)[3])       \
        : "r"((AF)[0]), "r"((AF)[1]), "r"((AF)[2]), "r"((AF)[3]),              \
          "r"(B0), "r"(B1))

// ---------------- TF32 GEMM, 128x128x16, double-buffered smem -------------
template<bool BSUM, bool COMBINE>
__global__ void __launch_bounds__(256) tgemm_k(
        const float* __restrict__ A, int lda, long sA,
        const float* __restrict__ Bm, const float* __restrict__ Bm2,
        int ldb, long sB,
        const float* __restrict__ bias,
        float* __restrict__ C, int ldc, long sC,
        int K) {
    __shared__ unsigned As[2][16 * TFPAD];
    __shared__ unsigned Bs[2][16 * TFPAD];
    long z = blockIdx.z;
    A += z * sA; Bm += z * sB; if (BSUM) Bm2 += z * sB; C += z * sC;
    const int m0 = blockIdx.y * 128, n0 = blockIdx.x * 128;
    const int tid = threadIdx.x;
    const int lane = tid & 31, wid = tid >> 5;
    const int warpM = wid >> 2, warpN = wid & 3;
    const int gid = lane >> 2, tig = lane & 3;
    const int am = tid >> 2, akq = tid & 3;
    const int bk = tid >> 5, bnq = tid & 31;
    const int axor = akq * 8;

    float acc[4][4][4] = {};
    const int NT = K / 16;

    float4 ra[2], rb[2];
    #pragma unroll
    for (int i = 0; i < 2; i++) {
        ra[i] = *(const float4*)&A[(long)(m0 + am + i * 64) * lda + akq * 4];
        long off = (long)(bk + i * 8) * ldb + n0 + bnq * 4;
        rb[i] = *(const float4*)&Bm[off];
        if (BSUM) {
            float4 e = *(const float4*)&Bm2[off];
            rb[i].x += e.x; rb[i].y += e.y; rb[i].z += e.z; rb[i].w += e.w;
        }
    }
    #pragma unroll
    for (int i = 0; i < 2; i++) {
        int mc = (am + i * 64) ^ axor;
        As[0][(akq * 4 + 0) * TFPAD + mc] = f2tf(ra[i].x);
        As[0][(akq * 4 + 1) * TFPAD + mc] = f2tf(ra[i].y);
        As[0][(akq * 4 + 2) * TFPAD + mc] = f2tf(ra[i].z);
        As[0][(akq * 4 + 3) * TFPAD + mc] = f2tf(ra[i].w);
        uint4 u; u.x = f2tf(rb[i].x); u.y = f2tf(rb[i].y); u.z = f2tf(rb[i].z); u.w = f2tf(rb[i].w);
        *(uint4*)&Bs[0][(bk + i * 8) * TFPAD + bnq * 4] = u;
    }
    __syncthreads();
    if (NT > 1) {
        #pragma unroll
        for (int i = 0; i < 2; i++) {
            ra[i] = *(const float4*)&A[(long)(m0 + am + i * 64) * lda + 16 + akq * 4];
            long off = (long)(16 + bk + i * 8) * ldb + n0 + bnq * 4;
            rb[i] = *(const float4*)&Bm[off];
            if (BSUM) {
                float4 e = *(const float4*)&Bm2[off];
                rb[i].x += e.x; rb[i].y += e.y; rb[i].z += e.z; rb[i].w += e.w;
            }
        }
    }

    for (int kt = 0; kt < NT; kt++) {
        const unsigned* Ac = As[kt & 1];
        const unsigned* Bc = Bs[kt & 1];
        #pragma unroll
        for (int ks = 0; ks < 2; ks++) {
            const int ko = ks * 8;
            const int x0 = (ko >> 2) << 3;
            const int x1 = x0 + 8;
            unsigned af[4][4], bf[4][2];
            #pragma unroll
            for (int mi = 0; mi < 4; mi++) {
                int mm = warpM * 64 + mi * 16;
                af[mi][0] = Ac[(ko + tig) * TFPAD + ((mm + gid) ^ x0)];
                af[mi][1] = Ac[(ko + tig) * TFPAD + ((mm + 8 + gid) ^ x0)];
                af[mi][2] = Ac[(ko + tig + 4) * TFPAD + ((mm + gid) ^ x1)];
                af[mi][3] = Ac[(ko + tig + 4) * TFPAD + ((mm + 8 + gid) ^ x1)];
            }
            #pragma unroll
            for (int ni = 0; ni < 4; ni++) {
                int nn = warpN * 32 + ni * 8;
                bf[ni][0] = Bc[(ko + tig) * TFPAD + nn + gid];
                bf[ni][1] = Bc[(ko + tig + 4) * TFPAD + nn + gid];
            }
            #pragma unroll
            for (int mi = 0; mi < 4; mi++)
                #pragma unroll
                for (int ni = 0; ni < 4; ni++)
                    MMA_TF32(acc[mi][ni], af[mi], bf[ni][0], bf[ni][1]);
        }
        if (kt + 1 < NT) {
            unsigned* An = As[(kt + 1) & 1];
            unsigned* Bn = Bs[(kt + 1) & 1];
            #pragma unroll
            for (int i = 0; i < 2; i++) {
                int mc = (am + i * 64) ^ axor;
                An[(akq * 4 + 0) * TFPAD + mc] = f2tf(ra[i].x);
                An[(akq * 4 + 1) * TFPAD + mc] = f2tf(ra[i].y);
                An[(akq * 4 + 2) * TFPAD + mc] = f2tf(ra[i].z);
                An[(akq * 4 + 3) * TFPAD + mc] = f2tf(ra[i].w);
                uint4 u; u.x = f2tf(rb[i].x); u.y = f2tf(rb[i].y); u.z = f2tf(rb[i].z); u.w = f2tf(rb[i].w);
                *(uint4*)&Bn[(bk + i * 8) * TFPAD + bnq * 4] = u;
            }
            if (kt + 2 < NT) {
                int k0 = (kt + 2) * 16;
                #pragma unroll
                for (int i = 0; i < 2; i++) {
                    ra[i] = *(const float4*)&A[(long)(m0 + am + i * 64) * lda + k0 + akq * 4];
                    long off = (long)(k0 + bk + i * 8) * ldb + n0 + bnq * 4;
                    rb[i] = *(const float4*)&Bm[off];
                    if (BSUM) {
                        float4 e = *(const float4*)&Bm2[off];
                        rb[i].x += e.x; rb[i].y += e.y; rb[i].z += e.z; rb[i].w += e.w;
                    }
                }
            }
        }
        __syncthreads();
    }

    #pragma unroll
    for (int mi = 0; mi < 4; mi++) {
        int r = m0 + warpM * 64 + mi * 16 + gid;
        #pragma unroll
        for (int ni = 0; ni < 4; ni++) {
            int cc = n0 + warpN * 32 + ni * 8 + tig * 2;
            float b0v = bias ? bias[cc] : 0.0f;
            float b1v = bias ? bias[cc + 1] : 0.0f;
            float2 v0, v1;
            if (COMBINE) {
                float a00 = 1.0f / (1.0f + __expf(-(acc[mi][ni][0] + b0v)));
                float a01 = 1.0f / (1.0f + __expf(-(acc[mi][ni][1] + b1v)));
                float a10 = 1.0f / (1.0f + __expf(-(acc[mi][ni][2] + b0v)));
                float a11 = 1.0f / (1.0f + __expf(-(acc[mi][ni][3] + b1v)));
                float2 lo0 = *(float2*)&g_lohtb[(long)r * 1024 + cc];
                float2 ht0 = *(float2*)&g_lohtb[(long)r * 1024 + 512 + cc];
                float2 lo1 = *(float2*)&g_lohtb[(long)(r + 8) * 1024 + cc];
                float2 ht1 = *(float2*)&g_lohtb[(long)(r + 8) * 1024 + 512 + cc];
                v0.x = lo0.x + ht0.x * a00; v0.y = lo0.y + ht0.y * a01;
                v1.x = lo1.x + ht1.x * a10; v1.y = lo1.y + ht1.y * a11;
            } else {
                v0.x = acc[mi][ni][0] + b0v; v0.y = acc[mi][ni][1] + b1v;
                v1.x = acc[mi][ni][2] + b0v; v1.y = acc[mi][ni][3] + b1v;
            }
            *(float2*)&C[(long)r * ldc + cc] = v0;
            *(float2*)&C[(long)(r + 8) * ldc + cc] = v1;
        }
    }
}

// ---------------- WIDE TF32 GEMM: 128x256x16, warp tile 64x64 --------------
constexpr int SMW_A = 16 * TFPAD;
constexpr int SMW_B = 16 * BWPAD;
constexpr int WSMEM_BYTES = (2 * SMW_A + 2 * SMW_B) * 4;   // 51200

__global__ void __launch_bounds__(256) tgemm_wide_k(
        const float* __restrict__ A, int lda,
        const float* __restrict__ Bm, int ldb,
        const float* __restrict__ bias,
        float* __restrict__ C, int ldc,
        int K) {
    extern __shared__ unsigned smw[];
    unsigned* As = smw;
    unsigned* Bs = smw + 2 * SMW_A;
    const int m0 = blockIdx.y * 128, n0 = blockIdx.x * 256;
    const int tid = threadIdx.x;
    const int lane = tid & 31, wid = tid >> 5;
    const int warpM = wid >> 2, warpN = wid & 3;
    const int gid = lane >> 2, tig = lane & 3;
    const int am = tid >> 2, akq = tid & 3;
    const int bk = tid >> 6, bnq = tid & 63;
    const int axor = akq * 8;

    float acc[4][8][4] = {};
    const int NT = K / 16;

    float4 ra[2], rb[4];
    #pragma unroll
    for (int i = 0; i < 2; i++)
        ra[i] = *(const float4*)&A[(long)(m0 + am + i * 64) * lda + akq * 4];
    #pragma unroll
    for (int i = 0; i < 4; i++)
        rb[i] = *(const float4*)&Bm[(long)(bk + i * 4) * ldb + n0 + bnq * 4];
    #pragma unroll
    for (int i = 0; i < 2; i++) {
        int mc = (am + i * 64) ^ axor;
        As[(akq * 4 + 0) * TFPAD + mc] = f2tf(ra[i].x);
        As[(akq * 4 + 1) * TFPAD + mc] = f2tf(ra[i].y);
        As[(akq * 4 + 2) * TFPAD + mc] = f2tf(ra[i].z);
        As[(akq * 4 + 3) * TFPAD + mc] = f2tf(ra[i].w);
    }
    #pragma unroll
    for (int i = 0; i < 4; i++) {
        uint4 u; u.x = f2tf(rb[i].x); u.y = f2tf(rb[i].y); u.z = f2tf(rb[i].z); u.w = f2tf(rb[i].w);
        *(uint4*)&Bs[(bk + i * 4) * BWPAD + bnq * 4] = u;
    }
    __syncthreads();
    if (NT > 1) {
        #pragma unroll
        for (int i = 0; i < 2; i++)
            ra[i] = *(const float4*)&A[(long)(m0 + am + i * 64) * lda + 16 + akq * 4];
        #pragma unroll
        for (int i = 0; i < 4; i++)
            rb[i] = *(const float4*)&Bm[(long)(16 + bk + i * 4) * ldb + n0 + bnq * 4];
    }

    for (int kt = 0; kt < NT; kt++) {
        const unsigned* Ac = As + (kt & 1) * SMW_A;
        const unsigned* Bc = Bs + (kt & 1) * SMW_B;
        #pragma unroll
        for (int ks = 0; ks < 2; ks++) {
            const int ko = ks * 8;
            const int x0 = (ko >> 2) << 3;
            const int x1 = x0 + 8;
            unsigned af[4][4], bf[8][2];
            #pragma unroll
            for (int mi = 0; mi < 4; mi++) {
                int mm = warpM * 64 + mi * 16;
                af[mi][0] = Ac[(ko + tig) * TFPAD + ((mm + gid) ^ x0)];
                af[mi][1] = Ac[(ko + tig) * TFPAD + ((mm + 8 + gid) ^ x0)];
                af[mi][2] = Ac[(ko + tig + 4) * TFPAD + ((mm + gid) ^ x1)];
                af[mi][3] = Ac[(ko + tig + 4) * TFPAD + ((mm + 8 + gid) ^ x1)];
            }
            #pragma unroll
            for (int ni = 0; ni < 8; ni++) {
                int nn = warpN * 64 + ni * 8;
                bf[ni][0] = Bc[(ko + tig) * BWPAD + nn + gid];
                bf[ni][1] = Bc[(ko + tig + 4) * BWPAD + nn + gid];
            }
            #pragma unroll
            for (int mi = 0; mi < 4; mi++)
                #pragma unroll
                for (int ni = 0; ni < 8; ni++)
                    MMA_TF32(acc[mi][ni], af[mi], bf[ni][0], bf[ni][1]);
        }
        if (kt + 1 < NT) {
            unsigned* An = As + ((kt + 1) & 1) * SMW_A;
            unsigned* Bn = Bs + ((kt + 1) & 1) * SMW_B;
            #pragma unroll
            for (int i = 0; i < 2; i++) {
                int mc = (am + i * 64) ^ axor;
                An[(akq * 4 + 0) * TFPAD + mc] = f2tf(ra[i].x);
                An[(akq * 4 + 1) * TFPAD + mc] = f2tf(ra[i].y);
                An[(akq * 4 + 2) * TFPAD + mc] = f2tf(ra[i].z);
                An[(akq * 4 + 3) * TFPAD + mc] = f2tf(ra[i].w);
            }
            #pragma unroll
            for (int i = 0; i < 4; i++) {
                uint4 u; u.x = f2tf(rb[i].x); u.y = f2tf(rb[i].y); u.z = f2tf(rb[i].z); u.w = f2tf(rb[i].w);
                *(uint4*)&Bn[(bk + i * 4) * BWPAD + bnq * 4] = u;
            }
            if (kt + 2 < NT) {
                int k0 = (kt + 2) * 16;
                #pragma unroll
                for (int i = 0; i < 2; i++)
                    ra[i] = *(const float4*)&A[(long)(m0 + am + i * 64) * lda + k0 + akq * 4];
                #pragma unroll
                for (int i = 0; i < 4; i++)
                    rb[i] = *(const float4*)&Bm[(long)(k0 + bk + i * 4) * ldb + n0 + bnq * 4];
            }
        }
        __syncthreads();
    }

    #pragma unroll
    for (int mi = 0; mi < 4; mi++) {
        int r = m0 + warpM * 64 + mi * 16 + gid;
        #pragma unroll
        for (int ni = 0; ni < 8; ni++) {
            int cc = n0 + warpN * 64 + ni * 8 + tig * 2;
            float b0v = bias ? bias[cc] : 0.0f;
            float b1v = bias ? bias[cc + 1] : 0.0f;
            float2 v0, v1;
            v0.x = acc[mi][ni][0] + b0v; v0.y = acc[mi][ni][1] + b1v;
            v1.x = acc[mi][ni][2] + b0v; v1.y = acc[mi][ni][3] + b1v;
            *(float2*)&C[(long)r * ldc + cc] = v0;
            *(float2*)&C[(long)(r + 8) * ldc + cc] = v1;
        }
    }
}

// ---------------- error-compensated TF32 GEMM (3-mma, ~fp32 accuracy) -----
__global__ void __launch_bounds__(256) tgemm3_k(
        const float* __restrict__ A, int lda,
        const float* __restrict__ Bm, int ldb,
        const float* __restrict__ bias,
        float* __restrict__ C, int ldc,
        int K) {
    __shared__ unsigned Ah[16 * TFPAD], Al[16 * TFPAD];
    __shared__ unsigned Bh[16 * TFPAD], Bl[16 * TFPAD];
    const int m0 = blockIdx.y * 128, n0 = blockIdx.x * 128;
    const int tid = threadIdx.x;
    const int lane = tid & 31, wid = tid >> 5;
    const int warpM = wid >> 2, warpN = wid & 3;
    const int gid = lane >> 2, tig = lane & 3;
    const int am = tid >> 2, akq = tid & 3;
    const int bk = tid >> 5, bnq = tid & 31;
    const int axor = akq * 8;

    float acc[4][4][4] = {};
    const int NT = K / 16;

    float4 ra[2], rb[2];
    #pragma unroll
    for (int i = 0; i < 2; i++) {
        ra[i] = *(const float4*)&A[(long)(m0 + am + i * 64) * lda + akq * 4];
        rb[i] = *(const float4*)&Bm[(long)(bk + i * 8) * ldb + n0 + bnq * 4];
    }

    for (int kt = 0; kt < NT; kt++) {
        #pragma unroll
        for (int i = 0; i < 2; i++) {
            int mc = (am + i * 64) ^ axor;
            float av[4] = {ra[i].x, ra[i].y, ra[i].z, ra[i].w};
            #pragma unroll
            for (int q = 0; q < 4; q++) {
                unsigned hb = f2tf(av[q]);
                Ah[(akq * 4 + q) * TFPAD + mc] = hb;
                Al[(akq * 4 + q) * TFPAD + mc] = f2tf(av[q] - __uint_as_float(hb));
            }
            float bv[4] = {rb[i].x, rb[i].y, rb[i].z, rb[i].w};
            uint4 uh, ul;
            unsigned* ph = &uh.x; unsigned* pl = &ul.x;
            #pragma unroll
            for (int q = 0; q < 4; q++) {
                unsigned hb = f2tf(bv[q]);
                ph[q] = hb;
                pl[q] = f2tf(bv[q] - __uint_as_float(hb));
            }
            *(uint4*)&Bh[(bk + i * 8) * TFPAD + bnq * 4] = uh;
            *(uint4*)&Bl[(bk + i * 8) * TFPAD + bnq * 4] = ul;
        }
        __syncthreads();
        if (kt + 1 < NT) {
            int k0 = (kt + 1) * 16;
            #pragma unroll
            for (int i = 0; i < 2; i++) {
                ra[i] = *(const float4*)&A[(long)(m0 + am + i * 64) * lda + k0 + akq * 4];
                rb[i] = *(const float4*)&Bm[(long)(k0 + bk + i * 8) * ldb + n0 + bnq * 4];
            }
        }
        #pragma unroll
        for (int ks = 0; ks < 2; ks++) {
            const int ko = ks * 8;
            const int x0 = (ko >> 2) << 3;
            const int x1 = x0 + 8;
            unsigned afh[4][4], afl[4][4], bfh[4][2], bfl[4][2];
            #pragma unroll
            for (int mi = 0; mi < 4; mi++) {
                int mm = warpM * 64 + mi * 16;
                afh[mi][0] = Ah[(ko + tig) * TFPAD + ((mm + gid) ^ x0)];
                afh[mi][1] = Ah[(ko + tig) * TFPAD + ((mm + 8 + gid) ^ x0)];
                afh[mi][2] = Ah[(ko + tig + 4) * TFPAD + ((mm + gid) ^ x1)];
                afh[mi][3] = Ah[(ko + tig + 4) * TFPAD + ((mm + 8 + gid) ^ x1)];
                afl[mi][0] = Al[(ko + tig) * TFPAD + ((mm + gid) ^ x0)];
                afl[mi][1] = Al[(ko + tig) * TFPAD + ((mm + 8 + gid) ^ x0)];
                afl[mi][2] = Al[(ko + tig + 4) * TFPAD + ((mm + gid) ^ x1)];
                afl[mi][3] = Al[(ko + tig + 4) * TFPAD + ((mm + 8 + gid) ^ x1)];
            }
            #pragma unroll
            for (int ni = 0; ni < 4; ni++) {
                int nn = warpN * 32 + ni * 8;
                bfh[ni][0] = Bh[(ko + tig) * TFPAD + nn + gid];
                bfh[ni][1] = Bh[(ko + tig + 4) * TFPAD + nn + gid];
                bfl[ni][0] = Bl[(ko + tig) * TFPAD + nn + gid];
                bfl[ni][1] = Bl[(ko + tig + 4) * TFPAD + nn + gid];
            }
            #pragma unroll
            for (int mi = 0; mi < 4; mi++)
                #pragma unroll
                for (int ni = 0; ni < 4; ni++) {
                    MMA_TF32(acc[mi][ni], afh[mi], bfl[ni][0], bfl[ni][1]);
                    MMA_TF32(acc[mi][ni], afl[mi], bfh[ni][0], bfh[ni][1]);
                    MMA_TF32(acc[mi][ni], afh[mi], bfh[ni][0], bfh[ni][1]);
                }
        }
        __syncthreads();
    }

    #pragma unroll
    for (int mi = 0; mi < 4; mi++) {
        int r = m0 + warpM * 64 + mi * 16 + gid;
        #pragma unroll
        for (int ni = 0; ni < 4; ni++) {
            int cc = n0 + warpN * 32 + ni * 8 + tig * 2;
            float b0v = bias ? bias[cc] : 0.0f;
            float b1v = bias ? bias[cc + 1] : 0.0f;
            float2 v0, v1;
            v0.x = acc[mi][ni][0] + b0v; v0.y = acc[mi][ni][1] + b1v;
            v1.x = acc[mi][ni][2] + b0v; v1.y = acc[mi][ni][3] + b1v;
            *(float2*)&C[(long)r * ldc + cc] = v0;
            *(float2*)&C[(long)(r + 8) * ldc + cc] = v1;
        }
    }
}

// ---------------- persistent LSTM (128 blocks, XOR-swizzled smem) ----------
// hs/ws rows (512 floats = 2KB) all start on bank 0 -> un-swizzled fragment
// reads were 2-way (hv) / 4-way (wv) bank-conflicted (53.5% L1 in ncu).
// Storage swizzle: float4 index s4 of row r lives at s4 ^ ((r&12)>>1).
// Within an 8-lane LDS phase the xor constant differs per bt (hv) / jt (wv),
// spreading the accesses over distinct bank groups -> conflict-free.
__device__ __forceinline__ int swz(int row, int s4) {
    return row * 128 + (s4 ^ ((row & 12) >> 1));
}

__global__ void __launch_bounds__(256) lstm_persist_k(const int* __restrict__ xlen,
                                                      const float* __restrict__ W_hh,
                                                      float* __restrict__ oat, int wo) {
    extern __shared__ float sm[];
    float* ws  = sm;            // [16][512]  swizzled
    float* hs  = sm + 8192;     // [16][512]  swizzled
    float* red = sm + 16384;    // [256][16]  swizzled

    const int tid = threadIdx.x;
    const int k0  = blockIdx.x * 4;
    const int sc = tid >> 4, bt = (tid >> 2) & 3, jt = tid & 3;
    float4* ws4 = (float4*)ws;
    float4* hs4 = (float4*)hs;

    // load weight slice once (swizzled store)
    {
        int r = tid >> 4, c16 = tid & 15;
        int g = r >> 2, dk = r & 3;
        const float4* src = (const float4*)&W_hh[(long)(g * 512 + k0 + dk) * 512];
        #pragma unroll
        for (int i = 0; i < 8; i++) {
            int s4 = c16 + i * 16;
            ws4[swz(r, s4)] = src[s4];
        }
    }

    int ub = tid >> 2, udk = tid & 3;
    float creg = 0.0f; int xl = 0;
    if (tid < 64) {
        creg = g_cbuf[ub * 512 + k0 + udk];
        xl   = xlen[ub];
    }

    const int hxor = bt * 2;     // (row&12)>>1 for rows bt*4+bi, bi<4
    const int wxor = jt * 2;     // ditto for rows jt*4+ji

    for (int t = 0; t < Tt; t++) {
        // load h into swizzled smem (L2-coherent loads)
        const float4* hin = (const float4*)g_hbuf[t & 1];
        #pragma unroll
        for (int i = 0; i < 8; i++) {
            int j = tid + i * 256;
            int row = j >> 7, s4 = j & 127;
            hs4[swz(row, s4)] = __ldcg(&hin[j]);
        }
        float gxr[4];
        if (tid < 64) {
            #pragma unroll
            for (int g = 0; g < 4; g++)
                gxr[g] = g_Gx[(long)(ub * Tt + t) * G4H + g * 512 + k0 + udk];
        }
        __syncthreads();

        float acc[4][4] = {};
        #pragma unroll
        for (int i = 0; i < 8; i++) {
            int s4b = sc + (i << 4);                    // float4 index 0..127
            float4 hv[4], wv[4];
            #pragma unroll
            for (int bi = 0; bi < 4; bi++)
                hv[bi] = hs4[(bt * 4 + bi) * 128 + (s4b ^ hxor)];
            #pragma unroll
            for (int ji = 0; ji < 4; ji++)
                wv[ji] = ws4[(jt * 4 + ji) * 128 + (s4b ^ wxor)];
            #pragma unroll
            for (int bi = 0; bi < 4; bi++)
                #pragma unroll
                for (int ji = 0; ji < 4; ji++)
                    acc[bi][ji] += hv[bi].x * wv[ji].x + hv[bi].y * wv[ji].y +
                                   hv[bi].z * wv[ji].z + hv[bi].w * wv[ji].w;
        }
        {
            int perm = bt * 4 + jt;
            #pragma unroll
            for (int bi = 0; bi < 4; bi++)
                #pragma unroll
                for (int ji = 0; ji < 4; ji++) {
                    int o = (bt * 4 + bi) * 16 + jt * 4 + ji;
                    red[o * 16 + (sc ^ perm)] = acc[bi][ji];
                }
        }
        __syncthreads();

        if (tid < 64) {
            int k = k0 + udk;
            float gate[4];
            #pragma unroll
            for (int g = 0; g < 4; g++) {
                int o = ub * 16 + g * 4 + udk;
                int perm = (o >> 6) * 4 + ((o >> 2) & 3);
                float s = 0.0f;
                #pragma unroll
                for (int scx = 0; scx < 16; scx++) s += red[o * 16 + (scx ^ perm)];
                gate[g] = gxr[g] + s;
            }
            float iv = 1.0f / (1.0f + __expf(-gate[0]));
            float fv = 1.0f / (1.0f + __expf(-gate[1]));
            float gg = tanhf(gate[2]);
            float ov = 1.0f / (1.0f + __expf(-gate[3]));
            float cn = fv * creg + iv * gg;
            float hn = ov * tanhf(cn);
            bool valid = (t < xl);
            creg = valid ? cn : creg;
            // read old h through the swizzle
            float hold = hs[swz(ub, k >> 2) * 4 + (k & 3)];
            float heff = valid ? hn : hold;
            __stcg(&g_hbuf[(t + 1) & 1][ub * 512 + k], heff);
            float lo = valid ? hn : 0.0f;
            long row = (long)(ub * Tt + t);
            g_lohtb[row * 1024 + k] = lo;
            g_attn_in[row * AIN + k] = lo;              // attention_input cols 0..511
            if (wo) oat[row * AIN + k] = lo;            // output slot 1
            __threadfence();
        }
        __syncthreads();

        if (t + 1 < Tt) {
            // round-5 barrier: single atomic arrival per block + one spinning
            // thread with HW nanosleep backoff.
            if (tid == 0) {
                atomicAdd(&g_bar, 1);
                int target = 128 * (t + 1);
                while (*(volatile int*)&g_bar < target) __nanosleep(64);
                __threadfence();
            }
            __syncthreads();
        }
    }
}

// ---------------- row softmax over S=512 -----------------------------------
__global__ void softmax_k() {
    __shared__ float red[8];
    float* p = g_att + (long)blockIdx.x * Ss;
    int tid = threadIdx.x;
    float m = -1e30f;
    for (int i = tid; i < Ss; i += 256) m = fmaxf(m, p[i]);
    #pragma unroll
    for (int o = 16; o; o >>= 1) m = fmaxf(m, __shfl_xor_sync(~0u, m, o));
    if ((tid & 31) == 0) red[tid >> 5] = m;
    __syncthreads();
    if (tid == 0) { float v = red[0]; for (int i = 1; i < 8; i++) v = fmaxf(v, red[i]); red[0] = v; }
    __syncthreads();
    m = red[0];
    __syncthreads();
    float s = 0.0f;
    for (int i = tid; i < Ss; i += 256) { float e = __expf(p[i] - m); p[i] = e; s += e; }
    #pragma unroll
    for (int o = 16; o; o >>= 1) s += __shfl_xor_sync(~0u, s, o);
    if ((tid & 31) == 0) red[tid >> 5] = s;
    __syncthreads();
    if (tid == 0) { float v = 0.0f; for (int i = 0; i < 8; i++) v += red[i]; red[0] = v; }
    __syncthreads();
    float inv = 1.0f / red[0];
    for (int i = tid; i < Ss; i += 256) p[i] *= inv;
}

// ---------------- host launcher --------------------------------------------
extern "C" void kernel_launch(void* const* d_in, const int* in_sizes, int n_in,
                              void* d_out, int out_size) {
    const int*   x       = (const int*)  d_in[0];
    const int*   xlen    = (const int*)  d_in[1];
    const float* h0      = (const float*)d_in[2];
    const float* c0      = (const float*)d_in[3];
    const float* eo      = (const float*)d_in[4];
    const float* emb     = (const float*)d_in[5];
    const float* W_att   = (const float*)d_in[6];
    const float* b_att   = (const float*)d_in[7];
    const float* W_ih    = (const float*)d_in[8];
    const float* W_hh    = (const float*)d_in[9];
    const float* b_ih    = (const float*)d_in[10];
    const float* b_hh    = (const float*)d_in[11];
    const float* W_align = (const float*)d_in[12];
    const float* b_align = (const float*)d_in[13];
    const float* W_out   = (const float*)d_in[14];
    const float* b_out   = (const float*)d_in[15];
    float* out = (float*)d_out;

    void *p_lin, *p_gx, *p_lohtb, *p_attn, *p_att, *p_op, *p_bsum, *p_wiht;
    cudaGetSymbolAddress(&p_lin,   g_lstm_in);
    cudaGetSymbolAddress(&p_gx,    g_Gx);
    cudaGetSymbolAddress(&p_lohtb, g_lohtb);
    cudaGetSymbolAddress(&p_attn,  g_attn_in);
    cudaGetSymbolAddress(&p_att,   g_att);
    cudaGetSymbolAddress(&p_op,    g_outpre);
    cudaGetSymbolAddress(&p_bsum,  g_bsum);
    cudaGetSymbolAddress(&p_wiht,  g_WihT);
    float* lin   = (float*)p_lin;   float* gx   = (float*)p_gx;
    float* lohtb = (float*)p_lohtb;
    float* attn  = (float*)p_attn;  float* att  = (float*)p_att;
    float* opre  = (float*)p_op;
    float* bsum  = (float*)p_bsum;  float* wihT = (float*)p_wiht;

    static bool attr_done = false;
    if (!attr_done) {
        cudaFuncSetAttribute(lstm_persist_k,
                             cudaFuncAttributeMaxDynamicSharedMemorySize, 84 * 1024);
        cudaFuncSetAttribute(tgemm_wide_k,
                             cudaFuncAttributeMaxDynamicSharedMemorySize, 64 * 1024);
        attr_done = true;
    }

    int wo = ((long)out_size >= OUT0 + OUT1) ? 1 : 0;
    int wt = ((long)out_size >= OUT0 + OUT1 + OUT2) ? 1 : 0;

    // (1) fused prep
    k_prep<<<(BT * KIN + 255) / 256, 256>>>(x, h0, c0, emb, b_ih, b_hh, out, wo, wt);

    // (2) W_ih transpose
    k_transpose_wih<<<dim3(KIN / 32, G4H / 32), dim3(32, 8)>>>(W_ih);

    // (3) Gx = lstm_input @ W_ih^T + (b_ih+b_hh)  — error-compensated tf32
    tgemm3_k<<<dim3(G4H / 128, BT / 128), 256>>>(
        lin, KIN, wihT, G4H, bsum, gx, G4H, KIN);

    // (4) LSTM recurrence — persistent kernel (ncu capture slot)
    lstm_persist_k<<<128, 256, (8192 + 8192 + 4096) * sizeof(float)>>>(
        xlen, W_hh, out + OUT0, wo);

    // (5) att logits = attn_in @ W_att + b_att
    tgemm_k<false, false><<<dim3(Ss / 128, BT / 128, 1), 256>>>(
        attn, AIN, 0, W_att, nullptr, Ss, 0, b_att, att, Ss, 0, AIN);

    // (6) softmax rows
    softmax_k<<<BT, 256>>>();

    // (7) h_t_bar[b] = soft[b] @ (eo[b] + eo[b+dir])
    tgemm_k<true, false><<<dim3(Hh / 128, Tt / 128, Bb), 256>>>(
        att, Ss, (long)Tt * Ss,
        eo, eo + BSH, Hh, (long)Ss * Hh,
        nullptr,
        lohtb + Hh, 1024, (long)Tt * 1024,
        Ss);

    // (8) align GEMM with fused combine epilogue
    tgemm_k<false, true><<<dim3(Hh / 128, BT / 128, 1), 256>>>(
        lohtb, 1024, 0, W_align, nullptr, Hh, 0, b_align, opre, Hh, 0, 1024);

    // (9) out = out_pre @ W_out + b_out  — wide tile 128x256
    tgemm_wide_k<<<dim3(Vv / 256, BT / 128), 256, WSMEM_BYTES>>>(
        opre, Hh, W_out, Vv, b_out, out, Vv, Hh);
}

// round 11
// speedup vs baseline: 1.5736x; 1.5736x over previous
#include <cuda_runtime.h>
#include <math.h>

// Problem dims
#define Vv 32000
#define Ee 512
#define Hh 512
#define Bb 16
#define Tt 128
#define Ss 512

constexpr int BT   = Bb * Tt;          // 2048
constexpr int G4H  = 4 * Hh;           // 2048
constexpr int KIN  = Ee + Hh;          // 1024
constexpr int AIN  = 2 * Hh + Ee;      // 1536
constexpr long OUT0 = (long)BT * Vv;
constexpr long OUT1 = (long)BT * AIN;
constexpr long OUT2 = BT;
constexpr long BSH  = (long)Bb * Ss * Hh;

// ---------------- scratch (device globals) --------------------------------
__device__ float g_lstm_in[BT * KIN];
__device__ float g_Gx[BT * G4H];
__device__ float g_WihT[KIN * G4H];       // W_ih transposed [KIN][4H]
__device__ float g_bsum[G4H];
__device__ float g_hbuf[2][Bb * Hh];
__device__ float g_cbuf[Bb * Hh];
__device__ float g_lohtb[BT * 1024];      // [ lstm_out | h_t_bar ]
__device__ float g_attn_in[BT * AIN];
__device__ float g_att[BT * Ss];
__device__ float g_outpre[BT * Hh];
__device__ int   g_bar;                   // persistent-LSTM grid barrier

// ---------------- fused prep kernel ----------------------------------------
__global__ void k_prep(const int* __restrict__ x,
                       const float* __restrict__ h0,
                       const float* __restrict__ c0,
                       const float* __restrict__ emb,
                       const float* __restrict__ b_ih,
                       const float* __restrict__ b_hh,
                       float* __restrict__ out, int wo, int wt) {
    int i = blockIdx.x * 256 + threadIdx.x;
    if (i == 0) g_bar = 0;
    if (i < G4H) g_bsum[i] = b_ih[i] + b_hh[i];
    if (i < Bb * Hh) { g_hbuf[0][i] = h0[i]; g_cbuf[i] = c0[i]; }
    if (i < BT && wt) out[OUT0 + OUT1 + i] = (float)((Ss / Tt) * (i % Tt));
    if (i >= BT * KIN) return;
    int bt = i / KIN, c = i % KIN;
    int b = bt / Tt;
    float v;
    if (c < Hh) v = h0[b * Hh + c] + c0[b * Hh + c];
    else        v = emb[(long)x[bt] * Ee + (c - Hh)];
    g_lstm_in[i] = v;
    long ao = (long)bt * AIN + Hh + c;     // attention_input cols 512..1535
    g_attn_in[ao] = v;
    if (wo) out[OUT0 + ao] = v;
}

// tiled transpose: W_ih [4H][KIN] -> g_WihT [KIN][4H]
__global__ void k_transpose_wih(const float* __restrict__ W) {
    __shared__ float tile[32][33];
    int bx = blockIdx.x * 32, by = blockIdx.y * 32;
    int x = bx + threadIdx.x;
    #pragma unroll
    for (int i = 0; i < 32; i += 8)
        tile[threadIdx.y + i][threadIdx.x] = W[(long)(by + threadIdx.y + i) * KIN + x];
    __syncthreads();
    int xo = by + threadIdx.x;
    #pragma unroll
    for (int i = 0; i < 32; i += 8)
        g_WihT[(long)(bx + threadIdx.y + i) * G4H + xo] = tile[threadIdx.x][threadIdx.y + i];
}

// ---------------- TF32 helpers --------------------------------------------
__device__ __forceinline__ unsigned f2tf(float f) {
    unsigned u;
    asm("cvt.rna.tf32.f32 %0, %1;" : "=r"(u) : "f"(f));
    return u;
}
#define TFPAD 136
#define BWPAD 264

#define MMA_TF32(ACC, AF, B0, B1)                                              \
    asm volatile(                                                              \
        "mma.sync.aligned.m16n8k8.row.col.f32.tf32.tf32.f32 "                  \
        "{%0,%1,%2,%3}, {%4,%5,%6,%7}, {%8,%9}, {%0,%1,%2,%3};"                \
        : "+f"((ACC)[0]), "+f"((ACC)[1]), "+f"((ACC)[2]), "+f"((ACC)[3])       \
        : "r"((AF)[0]), "r"((AF)[1]), "r"((AF)[2]), "r"((AF)[3]),              \
          "r"(B0), "r"(B1))

// ---------------- TF32 GEMM, 128x128x16, double-buffered smem -------------
template<bool BSUM, bool COMBINE>
__global__ void __launch_bounds__(256) tgemm_k(
        const float* __restrict__ A, int lda, long sA,
        const float* __restrict__ Bm, const float* __restrict__ Bm2,
        int ldb, long sB,
        const float* __restrict__ bias,
        float* __restrict__ C, int ldc, long sC,
        int K) {
    __shared__ unsigned As[2][16 * TFPAD];
    __shared__ unsigned Bs[2][16 * TFPAD];
    long z = blockIdx.z;
    A += z * sA; Bm += z * sB; if (BSUM) Bm2 += z * sB; C += z * sC;
    const int m0 = blockIdx.y * 128, n0 = blockIdx.x * 128;
    const int tid = threadIdx.x;
    const int lane = tid & 31, wid = tid >> 5;
    const int warpM = wid >> 2, warpN = wid & 3;
    const int gid = lane >> 2, tig = lane & 3;
    const int am = tid >> 2, akq = tid & 3;
    const int bk = tid >> 5, bnq = tid & 31;
    const int axor = akq * 8;

    float acc[4][4][4] = {};
    const int NT = K / 16;

    float4 ra[2], rb[2];
    #pragma unroll
    for (int i = 0; i < 2; i++) {
        ra[i] = *(const float4*)&A[(long)(m0 + am + i * 64) * lda + akq * 4];
        long off = (long)(bk + i * 8) * ldb + n0 + bnq * 4;
        rb[i] = *(const float4*)&Bm[off];
        if (BSUM) {
            float4 e = *(const float4*)&Bm2[off];
            rb[i].x += e.x; rb[i].y += e.y; rb[i].z += e.z; rb[i].w += e.w;
        }
    }
    #pragma unroll
    for (int i = 0; i < 2; i++) {
        int mc = (am + i * 64) ^ axor;
        As[0][(akq * 4 + 0) * TFPAD + mc] = f2tf(ra[i].x);
        As[0][(akq * 4 + 1) * TFPAD + mc] = f2tf(ra[i].y);
        As[0][(akq * 4 + 2) * TFPAD + mc] = f2tf(ra[i].z);
        As[0][(akq * 4 + 3) * TFPAD + mc] = f2tf(ra[i].w);
        uint4 u; u.x = f2tf(rb[i].x); u.y = f2tf(rb[i].y); u.z = f2tf(rb[i].z); u.w = f2tf(rb[i].w);
        *(uint4*)&Bs[0][(bk + i * 8) * TFPAD + bnq * 4] = u;
    }
    __syncthreads();
    if (NT > 1) {
        #pragma unroll
        for (int i = 0; i < 2; i++) {
            ra[i] = *(const float4*)&A[(long)(m0 + am + i * 64) * lda + 16 + akq * 4];
            long off = (long)(16 + bk + i * 8) * ldb + n0 + bnq * 4;
            rb[i] = *(const float4*)&Bm[off];
            if (BSUM) {
                float4 e = *(const float4*)&Bm2[off];
                rb[i].x += e.x; rb[i].y += e.y; rb[i].z += e.z; rb[i].w += e.w;
            }
        }
    }

    for (int kt = 0; kt < NT; kt++) {
        const unsigned* Ac = As[kt & 1];
        const unsigned* Bc = Bs[kt & 1];
        #pragma unroll
        for (int ks = 0; ks < 2; ks++) {
            const int ko = ks * 8;
            const int x0 = (ko >> 2) << 3;
            const int x1 = x0 + 8;
            unsigned af[4][4], bf[4][2];
            #pragma unroll
            for (int mi = 0; mi < 4; mi++) {
                int mm = warpM * 64 + mi * 16;
                af[mi][0] = Ac[(ko + tig) * TFPAD + ((mm + gid) ^ x0)];
                af[mi][1] = Ac[(ko + tig) * TFPAD + ((mm + 8 + gid) ^ x0)];
                af[mi][2] = Ac[(ko + tig + 4) * TFPAD + ((mm + gid) ^ x1)];
                af[mi][3] = Ac[(ko + tig + 4) * TFPAD + ((mm + 8 + gid) ^ x1)];
            }
            #pragma unroll
            for (int ni = 0; ni < 4; ni++) {
                int nn = warpN * 32 + ni * 8;
                bf[ni][0] = Bc[(ko + tig) * TFPAD + nn + gid];
                bf[ni][1] = Bc[(ko + tig + 4) * TFPAD + nn + gid];
            }
            #pragma unroll
            for (int mi = 0; mi < 4; mi++)
                #pragma unroll
                for (int ni = 0; ni < 4; ni++)
                    MMA_TF32(acc[mi][ni], af[mi], bf[ni][0], bf[ni][1]);
        }
        if (kt + 1 < NT) {
            unsigned* An = As[(kt + 1) & 1];
            unsigned* Bn = Bs[(kt + 1) & 1];
            #pragma unroll
            for (int i = 0; i < 2; i++) {
                int mc = (am + i * 64) ^ axor;
                An[(akq * 4 + 0) * TFPAD + mc] = f2tf(ra[i].x);
                An[(akq * 4 + 1) * TFPAD + mc] = f2tf(ra[i].y);
                An[(akq * 4 + 2) * TFPAD + mc] = f2tf(ra[i].z);
                An[(akq * 4 + 3) * TFPAD + mc] = f2tf(ra[i].w);
                uint4 u; u.x = f2tf(rb[i].x); u.y = f2tf(rb[i].y); u.z = f2tf(rb[i].z); u.w = f2tf(rb[i].w);
                *(uint4*)&Bn[(bk + i * 8) * TFPAD + bnq * 4] = u;
            }
            if (kt + 2 < NT) {
                int k0 = (kt + 2) * 16;
                #pragma unroll
                for (int i = 0; i < 2; i++) {
                    ra[i] = *(const float4*)&A[(long)(m0 + am + i * 64) * lda + k0 + akq * 4];
                    long off = (long)(k0 + bk + i * 8) * ldb + n0 + bnq * 4;
                    rb[i] = *(const float4*)&Bm[off];
                    if (BSUM) {
                        float4 e = *(const float4*)&Bm2[off];
                        rb[i].x += e.x; rb[i].y += e.y; rb[i].z += e.z; rb[i].w += e.w;
                    }
                }
            }
        }
        __syncthreads();
    }

    #pragma unroll
    for (int mi = 0; mi < 4; mi++) {
        int r = m0 + warpM * 64 + mi * 16 + gid;
        #pragma unroll
        for (int ni = 0; ni < 4; ni++) {
            int cc = n0 + warpN * 32 + ni * 8 + tig * 2;
            float b0v = bias ? bias[cc] : 0.0f;
            float b1v = bias ? bias[cc + 1] : 0.0f;
            float2 v0, v1;
            if (COMBINE) {
                float a00 = 1.0f / (1.0f + __expf(-(acc[mi][ni][0] + b0v)));
                float a01 = 1.0f / (1.0f + __expf(-(acc[mi][ni][1] + b1v)));
                float a10 = 1.0f / (1.0f + __expf(-(acc[mi][ni][2] + b0v)));
                float a11 = 1.0f / (1.0f + __expf(-(acc[mi][ni][3] + b1v)));
                float2 lo0 = *(float2*)&g_lohtb[(long)r * 1024 + cc];
                float2 ht0 = *(float2*)&g_lohtb[(long)r * 1024 + 512 + cc];
                float2 lo1 = *(float2*)&g_lohtb[(long)(r + 8) * 1024 + cc];
                float2 ht1 = *(float2*)&g_lohtb[(long)(r + 8) * 1024 + 512 + cc];
                v0.x = lo0.x + ht0.x * a00; v0.y = lo0.y + ht0.y * a01;
                v1.x = lo1.x + ht1.x * a10; v1.y = lo1.y + ht1.y * a11;
            } else {
                v0.x = acc[mi][ni][0] + b0v; v0.y = acc[mi][ni][1] + b1v;
                v1.x = acc[mi][ni][2] + b0v; v1.y = acc[mi][ni][3] + b1v;
            }
            *(float2*)&C[(long)r * ldc + cc] = v0;
            *(float2*)&C[(long)(r + 8) * ldc + cc] = v1;
        }
    }
}

// ---------------- WIDE TF32 GEMM: 128x256x16, warp tile 64x64 --------------
constexpr int SMW_A = 16 * TFPAD;
constexpr int SMW_B = 16 * BWPAD;
constexpr int WSMEM_BYTES = (2 * SMW_A + 2 * SMW_B) * 4;   // 51200

__global__ void __launch_bounds__(256) tgemm_wide_k(
        const float* __restrict__ A, int lda,
        const float* __restrict__ Bm, int ldb,
        const float* __restrict__ bias,
        float* __restrict__ C, int ldc,
        int K) {
    extern __shared__ unsigned smw[];
    unsigned* As = smw;
    unsigned* Bs = smw + 2 * SMW_A;
    const int m0 = blockIdx.y * 128, n0 = blockIdx.x * 256;
    const int tid = threadIdx.x;
    const int lane = tid & 31, wid = tid >> 5;
    const int warpM = wid >> 2, warpN = wid & 3;
    const int gid = lane >> 2, tig = lane & 3;
    const int am = tid >> 2, akq = tid & 3;
    const int bk = tid >> 6, bnq = tid & 63;
    const int axor = akq * 8;

    float acc[4][8][4] = {};
    const int NT = K / 16;

    float4 ra[2], rb[4];
    #pragma unroll
    for (int i = 0; i < 2; i++)
        ra[i] = *(const float4*)&A[(long)(m0 + am + i * 64) * lda + akq * 4];
    #pragma unroll
    for (int i = 0; i < 4; i++)
        rb[i] = *(const float4*)&Bm[(long)(bk + i * 4) * ldb + n0 + bnq * 4];
    #pragma unroll
    for (int i = 0; i < 2; i++) {
        int mc = (am + i * 64) ^ axor;
        As[(akq * 4 + 0) * TFPAD + mc] = f2tf(ra[i].x);
        As[(akq * 4 + 1) * TFPAD + mc] = f2tf(ra[i].y);
        As[(akq * 4 + 2) * TFPAD + mc] = f2tf(ra[i].z);
        As[(akq * 4 + 3) * TFPAD + mc] = f2tf(ra[i].w);
    }
    #pragma unroll
    for (int i = 0; i < 4; i++) {
        uint4 u; u.x = f2tf(rb[i].x); u.y = f2tf(rb[i].y); u.z = f2tf(rb[i].z); u.w = f2tf(rb[i].w);
        *(uint4*)&Bs[(bk + i * 4) * BWPAD + bnq * 4] = u;
    }
    __syncthreads();
    if (NT > 1) {
        #pragma unroll
        for (int i = 0; i < 2; i++)
            ra[i] = *(const float4*)&A[(long)(m0 + am + i * 64) * lda + 16 + akq * 4];
        #pragma unroll
        for (int i = 0; i < 4; i++)
            rb[i] = *(const float4*)&Bm[(long)(16 + bk + i * 4) * ldb + n0 + bnq * 4];
    }

    for (int kt = 0; kt < NT; kt++) {
        const unsigned* Ac = As + (kt & 1) * SMW_A;
        const unsigned* Bc = Bs + (kt & 1) * SMW_B;
        #pragma unroll
        for (int ks = 0; ks < 2; ks++) {
            const int ko = ks * 8;
            const int x0 = (ko >> 2) << 3;
            const int x1 = x0 + 8;
            unsigned af[4][4], bf[8][2];
            #pragma unroll
            for (int mi = 0; mi < 4; mi++) {
                int mm = warpM * 64 + mi * 16;
                af[mi][0] = Ac[(ko + tig) * TFPAD + ((mm + gid) ^ x0)];
                af[mi][1] = Ac[(ko + tig) * TFPAD + ((mm + 8 + gid) ^ x0)];
                af[mi][2] = Ac[(ko + tig + 4) * TFPAD + ((mm + gid) ^ x1)];
                af[mi][3] = Ac[(ko + tig + 4) * TFPAD + ((mm + 8 + gid) ^ x1)];
            }
            #pragma unroll
            for (int ni = 0; ni < 8; ni++) {
                int nn = warpN * 64 + ni * 8;
                bf[ni][0] = Bc[(ko + tig) * BWPAD + nn + gid];
                bf[ni][1] = Bc[(ko + tig + 4) * BWPAD + nn + gid];
            }
            #pragma unroll
            for (int mi = 0; mi < 4; mi++)
                #pragma unroll
                for (int ni = 0; ni < 8; ni++)
                    MMA_TF32(acc[mi][ni], af[mi], bf[ni][0], bf[ni][1]);
        }
        if (kt + 1 < NT) {
            unsigned* An = As + ((kt + 1) & 1) * SMW_A;
            unsigned* Bn = Bs + ((kt + 1) & 1) * SMW_B;
            #pragma unroll
            for (int i = 0; i < 2; i++) {
                int mc = (am + i * 64) ^ axor;
                An[(akq * 4 + 0) * TFPAD + mc] = f2tf(ra[i].x);
                An[(akq * 4 + 1) * TFPAD + mc] = f2tf(ra[i].y);
                An[(akq * 4 + 2) * TFPAD + mc] = f2tf(ra[i].z);
                An[(akq * 4 + 3) * TFPAD + mc] = f2tf(ra[i].w);
            }
            #pragma unroll
            for (int i = 0; i < 4; i++) {
                uint4 u; u.x = f2tf(rb[i].x); u.y = f2tf(rb[i].y); u.z = f2tf(rb[i].z); u.w = f2tf(rb[i].w);
                *(uint4*)&Bn[(bk + i * 4) * BWPAD + bnq * 4] = u;
            }
            if (kt + 2 < NT) {
                int k0 = (kt + 2) * 16;
                #pragma unroll
                for (int i = 0; i < 2; i++)
                    ra[i] = *(const float4*)&A[(long)(m0 + am + i * 64) * lda + k0 + akq * 4];
                #pragma unroll
                for (int i = 0; i < 4; i++)
                    rb[i] = *(const float4*)&Bm[(long)(k0 + bk + i * 4) * ldb + n0 + bnq * 4];
            }
        }
        __syncthreads();
    }

    #pragma unroll
    for (int mi = 0; mi < 4; mi++) {
        int r = m0 + warpM * 64 + mi * 16 + gid;
        #pragma unroll
        for (int ni = 0; ni < 8; ni++) {
            int cc = n0 + warpN * 64 + ni * 8 + tig * 2;
            float b0v = bias ? bias[cc] : 0.0f;
            float b1v = bias ? bias[cc + 1] : 0.0f;
            float2 v0, v1;
            v0.x = acc[mi][ni][0] + b0v; v0.y = acc[mi][ni][1] + b1v;
            v1.x = acc[mi][ni][2] + b0v; v1.y = acc[mi][ni][3] + b1v;
            *(float2*)&C[(long)r * ldc + cc] = v0;
            *(float2*)&C[(long)(r + 8) * ldc + cc] = v1;
        }
    }
}

// ---------------- error-compensated TF32 GEMM (3-mma, ~fp32 accuracy) -----
__global__ void __launch_bounds__(256) tgemm3_k(
        const float* __restrict__ A, int lda,
        const float* __restrict__ Bm, int ldb,
        const float* __restrict__ bias,
        float* __restrict__ C, int ldc,
        int K) {
    __shared__ unsigned Ah[16 * TFPAD], Al[16 * TFPAD];
    __shared__ unsigned Bh[16 * TFPAD], Bl[16 * TFPAD];
    const int m0 = blockIdx.y * 128, n0 = blockIdx.x * 128;
    const int tid = threadIdx.x;
    const int lane = tid & 31, wid = tid >> 5;
    const int warpM = wid >> 2, warpN = wid & 3;
    const int gid = lane >> 2, tig = lane & 3;
    const int am = tid >> 2, akq = tid & 3;
    const int bk = tid >> 5, bnq = tid & 31;
    const int axor = akq * 8;

    float acc[4][4][4] = {};
    const int NT = K / 16;

    float4 ra[2], rb[2];
    #pragma unroll
    for (int i = 0; i < 2; i++) {
        ra[i] = *(const float4*)&A[(long)(m0 + am + i * 64) * lda + akq * 4];
        rb[i] = *(const float4*)&Bm[(long)(bk + i * 8) * ldb + n0 + bnq * 4];
    }

    for (int kt = 0; kt < NT; kt++) {
        #pragma unroll
        for (int i = 0; i < 2; i++) {
            int mc = (am + i * 64) ^ axor;
            float av[4] = {ra[i].x, ra[i].y, ra[i].z, ra[i].w};
            #pragma unroll
            for (int q = 0; q < 4; q++) {
                unsigned hb = f2tf(av[q]);
                Ah[(akq * 4 + q) * TFPAD + mc] = hb;
                Al[(akq * 4 + q) * TFPAD + mc] = f2tf(av[q] - __uint_as_float(hb));
            }
            float bv[4] = {rb[i].x, rb[i].y, rb[i].z, rb[i].w};
            uint4 uh, ul;
            unsigned* ph = &uh.x; unsigned* pl = &ul.x;
            #pragma unroll
            for (int q = 0; q < 4; q++) {
                unsigned hb = f2tf(bv[q]);
                ph[q] = hb;
                pl[q] = f2tf(bv[q] - __uint_as_float(hb));
            }
            *(uint4*)&Bh[(bk + i * 8) * TFPAD + bnq * 4] = uh;
            *(uint4*)&Bl[(bk + i * 8) * TFPAD + bnq * 4] = ul;
        }
        __syncthreads();
        if (kt + 1 < NT) {
            int k0 = (kt + 1) * 16;
            #pragma unroll
            for (int i = 0; i < 2; i++) {
                ra[i] = *(const float4*)&A[(long)(m0 + am + i * 64) * lda + k0 + akq * 4];
                rb[i] = *(const float4*)&Bm[(long)(k0 + bk + i * 8) * ldb + n0 + bnq * 4];
            }
        }
        #pragma unroll
        for (int ks = 0; ks < 2; ks++) {
            const int ko = ks * 8;
            const int x0 = (ko >> 2) << 3;
            const int x1 = x0 + 8;
            unsigned afh[4][4], afl[4][4], bfh[4][2], bfl[4][2];
            #pragma unroll
            for (int mi = 0; mi < 4; mi++) {
                int mm = warpM * 64 + mi * 16;
                afh[mi][0] = Ah[(ko + tig) * TFPAD + ((mm + gid) ^ x0)];
                afh[mi][1] = Ah[(ko + tig) * TFPAD + ((mm + 8 + gid) ^ x0)];
                afh[mi][2] = Ah[(ko + tig + 4) * TFPAD + ((mm + gid) ^ x1)];
                afh[mi][3] = Ah[(ko + tig + 4) * TFPAD + ((mm + 8 + gid) ^ x1)];
                afl[mi][0] = Al[(ko + tig) * TFPAD + ((mm + gid) ^ x0)];
                afl[mi][1] = Al[(ko + tig) * TFPAD + ((mm + 8 + gid) ^ x0)];
                afl[mi][2] = Al[(ko + tig + 4) * TFPAD + ((mm + gid) ^ x1)];
                afl[mi][3] = Al[(ko + tig + 4) * TFPAD + ((mm + 8 + gid) ^ x1)];
            }
            #pragma unroll
            for (int ni = 0; ni < 4; ni++) {
                int nn = warpN * 32 + ni * 8;
                bfh[ni][0] = Bh[(ko + tig) * TFPAD + nn + gid];
                bfh[ni][1] = Bh[(ko + tig + 4) * TFPAD + nn + gid];
                bfl[ni][0] = Bl[(ko + tig) * TFPAD + nn + gid];
                bfl[ni][1] = Bl[(ko + tig + 4) * TFPAD + nn + gid];
            }
            #pragma unroll
            for (int mi = 0; mi < 4; mi++)
                #pragma unroll
                for (int ni = 0; ni < 4; ni++) {
                    MMA_TF32(acc[mi][ni], afh[mi], bfl[ni][0], bfl[ni][1]);
                    MMA_TF32(acc[mi][ni], afl[mi], bfh[ni][0], bfh[ni][1]);
                    MMA_TF32(acc[mi][ni], afh[mi], bfh[ni][0], bfh[ni][1]);
                }
        }
        __syncthreads();
    }

    #pragma unroll
    for (int mi = 0; mi < 4; mi++) {
        int r = m0 + warpM * 64 + mi * 16 + gid;
        #pragma unroll
        for (int ni = 0; ni < 4; ni++) {
            int cc = n0 + warpN * 32 + ni * 8 + tig * 2;
            float b0v = bias ? bias[cc] : 0.0f;
            float b1v = bias ? bias[cc + 1] : 0.0f;
            float2 v0, v1;
            v0.x = acc[mi][ni][0] + b0v; v0.y = acc[mi][ni][1] + b1v;
            v1.x = acc[mi][ni][2] + b0v; v1.y = acc[mi][ni][3] + b1v;
            *(float2*)&C[(long)r * ldc + cc] = v0;
            *(float2*)&C[(long)(r + 8) * ldc + cc] = v1;
        }
    }
}

// ---------------- persistent LSTM (latency-diet barrier) -------------------
__device__ __forceinline__ int swz(int row, int s4) {
    return row * 128 + (s4 ^ ((row & 12) >> 1));
}
__device__ __forceinline__ float tanh_apx(float x) {
    float y;
    asm("tanh.approx.f32 %0, %1;" : "=f"(y) : "f"(x));
    return y;
}

__global__ void __launch_bounds__(256) lstm_persist_k(const int* __restrict__ xlen,
                                                      const float* __restrict__ W_hh,
                                                      float* __restrict__ oat, int wo) {
    extern __shared__ float sm[];
    float* ws  = sm;            // [16][512]  swizzled
    float* hs  = sm + 8192;     // [16][512]  swizzled
    float* red = sm + 16384;    // [256][16]  swizzled

    const int tid = threadIdx.x;
    const int k0  = blockIdx.x * 4;
    const int sc = tid >> 4, bt = (tid >> 2) & 3, jt = tid & 3;
    float4* ws4 = (float4*)ws;
    float4* hs4 = (float4*)hs;

    // load weight slice once (swizzled store)
    {
        int r = tid >> 4, c16 = tid & 15;
        int g = r >> 2, dk = r & 3;
        const float4* src = (const float4*)&W_hh[(long)(g * 512 + k0 + dk) * 512];
        #pragma unroll
        for (int i = 0; i < 8; i++) {
            int s4 = c16 + i * 16;
            ws4[swz(r, s4)] = src[s4];
        }
    }

    int ub = tid >> 2, udk = tid & 3;
    float creg = 0.0f; int xl = 0;
    if (tid < 64) {
        creg = g_cbuf[ub * 512 + k0 + udk];
        xl   = xlen[ub];
    }

    const int hxor = bt * 2;
    const int wxor = jt * 2;

    int* barp;
    asm("cvta.global.u64 %0, g_bar;" : "=l"(barp));

    for (int t = 0; t < Tt; t++) {
        // load h into swizzled smem (L2-coherent loads)
        const float4* hin = (const float4*)g_hbuf[t & 1];
        #pragma unroll
        for (int i = 0; i < 8; i++) {
            int j = tid + i * 256;
            int row = j >> 7, s4 = j & 127;
            hs4[swz(row, s4)] = __ldcg(&hin[j]);
        }
        float gxr[4];
        if (tid < 64) {
            #pragma unroll
            for (int g = 0; g < 4; g++)
                gxr[g] = g_Gx[(long)(ub * Tt + t) * G4H + g * 512 + k0 + udk];
        }
        __syncthreads();

        float acc[4][4] = {};
        #pragma unroll
        for (int i = 0; i < 8; i++) {
            int s4b = sc + (i << 4);
            float4 hv[4], wv[4];
            #pragma unroll
            for (int bi = 0; bi < 4; bi++)
                hv[bi] = hs4[(bt * 4 + bi) * 128 + (s4b ^ hxor)];
            #pragma unroll
            for (int ji = 0; ji < 4; ji++)
                wv[ji] = ws4[(jt * 4 + ji) * 128 + (s4b ^ wxor)];
            #pragma unroll
            for (int bi = 0; bi < 4; bi++)
                #pragma unroll
                for (int ji = 0; ji < 4; ji++)
                    acc[bi][ji] += hv[bi].x * wv[ji].x + hv[bi].y * wv[ji].y +
                                   hv[bi].z * wv[ji].z + hv[bi].w * wv[ji].w;
        }
        {
            int perm = bt * 4 + jt;
            #pragma unroll
            for (int bi = 0; bi < 4; bi++)
                #pragma unroll
                for (int ji = 0; ji < 4; ji++) {
                    int o = (bt * 4 + bi) * 16 + jt * 4 + ji;
                    red[o * 16 + (sc ^ perm)] = acc[bi][ji];
                }
        }
        __syncthreads();

        if (tid < 64) {
            int k = k0 + udk;
            float gate[4];
            #pragma unroll
            for (int g = 0; g < 4; g++) {
                int o = ub * 16 + g * 4 + udk;
                int perm = (o >> 6) * 4 + ((o >> 2) & 3);
                float s = 0.0f;
                #pragma unroll
                for (int scx = 0; scx < 16; scx++) s += red[o * 16 + (scx ^ perm)];
                gate[g] = gxr[g] + s;
            }
            float iv = 1.0f / (1.0f + __expf(-gate[0]));
            float fv = 1.0f / (1.0f + __expf(-gate[1]));
            float gg = tanh_apx(gate[2]);
            float ov = 1.0f / (1.0f + __expf(-gate[3]));
            float cn = fv * creg + iv * gg;
            float hn = ov * tanh_apx(cn);
            bool valid = (t < xl);
            creg = valid ? cn : creg;
            float hold = hs[swz(ub, k >> 2) * 4 + (k & 3)];
            float heff = valid ? hn : hold;
            __stcg(&g_hbuf[(t + 1) & 1][ub * 512 + k], heff);
            float lo = valid ? hn : 0.0f;
            long row = (long)(ub * Tt + t);
            g_lohtb[row * 1024 + k] = lo;
            g_attn_in[row * AIN + k] = lo;
            if (wo) oat[row * AIN + k] = lo;
            // NOTE: no per-thread threadfence — fence elevated to tid0 below
        }
        __syncthreads();

        if (t + 1 < Tt) {
            // fence-elevated grid barrier (cooperative-groups pattern):
            // syncthreads above orders this block's stores; tid0 release-fences
            // once, arrives with a relaxed atomic, and acquire-spins (no
            // nanosleep — one L2 line, one polling thread per SM).
            if (tid == 0) {
                asm volatile("fence.acq_rel.gpu;" ::: "memory");
                atomicAdd(barp, 1);
                int target = 128 * (t + 1);
                int v;
                do {
                    asm volatile("ld.global.acquire.gpu.b32 %0, [%1];"
                                 : "=r"(v) : "l"(barp) : "memory");
                } while (v < target);
            }
            __syncthreads();
        }
    }
}

// ---------------- row softmax over S=512 -----------------------------------
__global__ void softmax_k() {
    __shared__ float red[8];
    float* p = g_att + (long)blockIdx.x * Ss;
    int tid = threadIdx.x;
    float m = -1e30f;
    for (int i = tid; i < Ss; i += 256) m = fmaxf(m, p[i]);
    #pragma unroll
    for (int o = 16; o; o >>= 1) m = fmaxf(m, __shfl_xor_sync(~0u, m, o));
    if ((tid & 31) == 0) red[tid >> 5] = m;
    __syncthreads();
    if (tid == 0) { float v = red[0]; for (int i = 1; i < 8; i++) v = fmaxf(v, red[i]); red[0] = v; }
    __syncthreads();
    m = red[0];
    __syncthreads();
    float s = 0.0f;
    for (int i = tid; i < Ss; i += 256) { float e = __expf(p[i] - m); p[i] = e; s += e; }
    #pragma unroll
    for (int o = 16; o; o >>= 1) s += __shfl_xor_sync(~0u, s, o);
    if ((tid & 31) == 0) red[tid >> 5] = s;
    __syncthreads();
    if (tid == 0) { float v = 0.0f; for (int i = 0; i < 8; i++) v += red[i]; red[0] = v; }
    __syncthreads();
    float inv = 1.0f / red[0];
    for (int i = tid; i < Ss; i += 256) p[i] *= inv;
}

// ---------------- host launcher --------------------------------------------
extern "C" void kernel_launch(void* const* d_in, const int* in_sizes, int n_in,
                              void* d_out, int out_size) {
    const int*   x       = (const int*)  d_in[0];
    const int*   xlen    = (const int*)  d_in[1];
    const float* h0      = (const float*)d_in[2];
    const float* c0      = (const float*)d_in[3];
    const float* eo      = (const float*)d_in[4];
    const float* emb     = (const float*)d_in[5];
    const float* W_att   = (const float*)d_in[6];
    const float* b_att   = (const float*)d_in[7];
    const float* W_ih    = (const float*)d_in[8];
    const float* W_hh    = (const float*)d_in[9];
    const float* b_ih    = (const float*)d_in[10];
    const float* b_hh    = (const float*)d_in[11];
    const float* W_align = (const float*)d_in[12];
    const float* b_align = (const float*)d_in[13];
    const float* W_out   = (const float*)d_in[14];
    const float* b_out   = (const float*)d_in[15];
    float* out = (float*)d_out;

    void *p_lin, *p_gx, *p_lohtb, *p_attn, *p_att, *p_op, *p_bsum, *p_wiht;
    cudaGetSymbolAddress(&p_lin,   g_lstm_in);
    cudaGetSymbolAddress(&p_gx,    g_Gx);
    cudaGetSymbolAddress(&p_lohtb, g_lohtb);
    cudaGetSymbolAddress(&p_attn,  g_attn_in);
    cudaGetSymbolAddress(&p_att,   g_att);
    cudaGetSymbolAddress(&p_op,    g_outpre);
    cudaGetSymbolAddress(&p_bsum,  g_bsum);
    cudaGetSymbolAddress(&p_wiht,  g_WihT);
    float* lin   = (float*)p_lin;   float* gx   = (float*)p_gx;
    float* lohtb = (float*)p_lohtb;
    float* attn  = (float*)p_attn;  float* att  = (float*)p_att;
    float* opre  = (float*)p_op;
    float* bsum  = (float*)p_bsum;  float* wihT = (float*)p_wiht;

    static bool attr_done = false;
    if (!attr_done) {
        cudaFuncSetAttribute(lstm_persist_k,
                             cudaFuncAttributeMaxDynamicSharedMemorySize, 84 * 1024);
        cudaFuncSetAttribute(tgemm_wide_k,
                             cudaFuncAttributeMaxDynamicSharedMemorySize, 64 * 1024);
        attr_done = true;
    }

    int wo = ((long)out_size >= OUT0 + OUT1) ? 1 : 0;
    int wt = ((long)out_size >= OUT0 + OUT1 + OUT2) ? 1 : 0;

    // (1) fused prep
    k_prep<<<(BT * KIN + 255) / 256, 256>>>(x, h0, c0, emb, b_ih, b_hh, out, wo, wt);

    // (2) W_ih transpose
    k_transpose_wih<<<dim3(KIN / 32, G4H / 32), dim3(32, 8)>>>(W_ih);

    // (3) Gx = lstm_input @ W_ih^T + (b_ih+b_hh)  — error-compensated tf32
    tgemm3_k<<<dim3(G4H / 128, BT / 128), 256>>>(
        lin, KIN, wihT, G4H, bsum, gx, G4H, KIN);

    // (4) LSTM recurrence — persistent kernel (ncu capture slot)
    lstm_persist_k<<<128, 256, (8192 + 8192 + 4096) * sizeof(float)>>>(
        xlen, W_hh, out + OUT0, wo);

    // (5) att logits = attn_in @ W_att + b_att
    tgemm_k<false, false><<<dim3(Ss / 128, BT / 128, 1), 256>>>(
        attn, AIN, 0, W_att, nullptr, Ss, 0, b_att, att, Ss, 0, AIN);

    // (6) softmax rows
    softmax_k<<<BT, 256>>>();

    // (7) h_t_bar[b] = soft[b] @ (eo[b] + eo[b+dir])
    tgemm_k<true, false><<<dim3(Hh / 128, Tt / 128, Bb), 256>>>(
        att, Ss, (long)Tt * Ss,
        eo, eo + BSH, Hh, (long)Ss * Hh,
        nullptr,
        lohtb + Hh, 1024, (long)Tt * 1024,
        Ss);

    // (8) align GEMM with fused combine epilogue
    tgemm_k<false, true><<<dim3(Hh / 128, BT / 128, 1), 256>>>(
        lohtb, 1024, 0, W_align, nullptr, Hh, 0, b_align, opre, Hh, 0, 1024);

    // (9) out = out_pre @ W_out + b_out  — wide tile 128x256
    tgemm_wide_k<<<dim3(Vv / 256, BT / 128), 256, WSMEM_BYTES>>>(
        opre, Hh, W_out, Vv, b_out, out, Vv, Hh);
}

// round 13
// speedup vs baseline: 1.6783x; 1.0666x over previous
#include <cuda_runtime.h>
#include <math.h>

// Problem dims
#define Vv 32000
#define Ee 512
#define Hh 512
#define Bb 16
#define Tt 128
#define Ss 512

constexpr int BT   = Bb * Tt;          // 2048
constexpr int G4H  = 4 * Hh;           // 2048
constexpr int KIN  = Ee + Hh;          // 1024
constexpr int AIN  = 2 * Hh + Ee;      // 1536
constexpr long OUT0 = (long)BT * Vv;
constexpr long OUT1 = (long)BT * AIN;
constexpr long OUT2 = BT;
constexpr long BSH  = (long)Bb * Ss * Hh;

// ---------------- scratch (device globals) --------------------------------
__device__ float g_lstm_in[BT * KIN];
__device__ float g_Gx[BT * G4H];
__device__ float g_WihT[KIN * G4H];       // W_ih transposed [KIN][4H]
__device__ float g_bsum[G4H];
__device__ float g_hbuf[2][Bb * Hh];
__device__ float g_cbuf[Bb * Hh];
__device__ float g_lohtb[BT * 1024];      // [ lstm_out | h_t_bar ]
__device__ float g_attn_in[BT * AIN];
__device__ float g_att[BT * Ss];
__device__ float g_outpre[BT * Hh];
__device__ int   g_bar;                   // persistent-LSTM grid barrier

// ---------------- fused prep kernel ----------------------------------------
__global__ void k_prep(const int* __restrict__ x,
                       const float* __restrict__ h0,
                       const float* __restrict__ c0,
                       const float* __restrict__ emb,
                       const float* __restrict__ b_ih,
                       const float* __restrict__ b_hh,
                       float* __restrict__ out, int wo, int wt) {
    int i = blockIdx.x * 256 + threadIdx.x;
    if (i == 0) g_bar = 0;
    if (i < G4H) g_bsum[i] = b_ih[i] + b_hh[i];
    if (i < Bb * Hh) { g_hbuf[0][i] = h0[i]; g_cbuf[i] = c0[i]; }
    if (i < BT && wt) out[OUT0 + OUT1 + i] = (float)((Ss / Tt) * (i % Tt));
    if (i >= BT * KIN) return;
    int bt = i / KIN, c = i % KIN;
    int b = bt / Tt;
    float v;
    if (c < Hh) v = h0[b * Hh + c] + c0[b * Hh + c];
    else        v = emb[(long)x[bt] * Ee + (c - Hh)];
    g_lstm_in[i] = v;
    long ao = (long)bt * AIN + Hh + c;     // attention_input cols 512..1535
    g_attn_in[ao] = v;
    if (wo) out[OUT0 + ao] = v;
}

// tiled transpose: W_ih [4H][KIN] -> g_WihT [KIN][4H]
__global__ void k_transpose_wih(const float* __restrict__ W) {
    __shared__ float tile[32][33];
    int bx = blockIdx.x * 32, by = blockIdx.y * 32;
    int x = bx + threadIdx.x;
    #pragma unroll
    for (int i = 0; i < 32; i += 8)
        tile[threadIdx.y + i][threadIdx.x] = W[(long)(by + threadIdx.y + i) * KIN + x];
    __syncthreads();
    int xo = by + threadIdx.x;
    #pragma unroll
    for (int i = 0; i < 32; i += 8)
        g_WihT[(long)(bx + threadIdx.y + i) * G4H + xo] = tile[threadIdx.x][threadIdx.y + i];
}

// ---------------- TF32 helpers --------------------------------------------
__device__ __forceinline__ unsigned f2tf(float f) {
    unsigned u;
    asm("cvt.rna.tf32.f32 %0, %1;" : "=r"(u) : "f"(f));
    return u;
}
#define TFPAD 136
#define BWPAD 264

#define MMA_TF32(ACC, AF, B0, B1)                                              \
    asm volatile(                                                              \
        "mma.sync.aligned.m16n8k8.row.col.f32.tf32.tf32.f32 "                  \
        "{%0,%1,%2,%3}, {%4,%5,%6,%7}, {%8,%9}, {%0,%1,%2,%3};"                \
        : "+f"((ACC)[0]), "+f"((ACC)[1]), "+f"((ACC)[2]), "+f"((ACC)[3])       \
        : "r"((AF)[0]), "r"((AF)[1]), "r"((AF)[2]), "r"((AF)[3]),              \
          "r"(B0), "r"(B1))

// ---------------- TF32 GEMM, 128x128x16, double-buffered smem -------------
// C[z] = A[z] @ B[z] + bias.
// BSUM:    B tile is Bm[off] + Bm2[off] (direction-summed encoder)
// COMBINE: epilogue writes C = lo + htb * sigmoid(acc + bias)
template<bool BSUM, bool COMBINE>
__global__ void __launch_bounds__(256) tgemm_k(
        const float* __restrict__ A, int lda, long sA,
        const float* __restrict__ Bm, const float* __restrict__ Bm2,
        int ldb, long sB,
        const float* __restrict__ bias,
        float* __restrict__ C, int ldc, long sC,
        int K) {
    __shared__ unsigned As[2][16 * TFPAD];
    __shared__ unsigned Bs[2][16 * TFPAD];
    long z = blockIdx.z;
    A += z * sA; Bm += z * sB; if (BSUM) Bm2 += z * sB; C += z * sC;
    const int m0 = blockIdx.y * 128, n0 = blockIdx.x * 128;
    const int tid = threadIdx.x;
    const int lane = tid & 31, wid = tid >> 5;
    const int warpM = wid >> 2, warpN = wid & 3;
    const int gid = lane >> 2, tig = lane & 3;
    const int am = tid >> 2, akq = tid & 3;
    const int bk = tid >> 5, bnq = tid & 31;
    const int axor = akq * 8;

    float acc[4][4][4] = {};
    const int NT = K / 16;

    float4 ra[2], rb[2];
    #pragma unroll
    for (int i = 0; i < 2; i++) {
        ra[i] = *(const float4*)&A[(long)(m0 + am + i * 64) * lda + akq * 4];
        long off = (long)(bk + i * 8) * ldb + n0 + bnq * 4;
        rb[i] = *(const float4*)&Bm[off];
        if (BSUM) {
            float4 e = *(const float4*)&Bm2[off];
            rb[i].x += e.x; rb[i].y += e.y; rb[i].z += e.z; rb[i].w += e.w;
        }
    }
    #pragma unroll
    for (int i = 0; i < 2; i++) {
        int mc = (am + i * 64) ^ axor;
        As[0][(akq * 4 + 0) * TFPAD + mc] = f2tf(ra[i].x);
        As[0][(akq * 4 + 1) * TFPAD + mc] = f2tf(ra[i].y);
        As[0][(akq * 4 + 2) * TFPAD + mc] = f2tf(ra[i].z);
        As[0][(akq * 4 + 3) * TFPAD + mc] = f2tf(ra[i].w);
        uint4 u; u.x = f2tf(rb[i].x); u.y = f2tf(rb[i].y); u.z = f2tf(rb[i].z); u.w = f2tf(rb[i].w);
        *(uint4*)&Bs[0][(bk + i * 8) * TFPAD + bnq * 4] = u;
    }
    __syncthreads();
    if (NT > 1) {
        #pragma unroll
        for (int i = 0; i < 2; i++) {
            ra[i] = *(const float4*)&A[(long)(m0 + am + i * 64) * lda + 16 + akq * 4];
            long off = (long)(16 + bk + i * 8) * ldb + n0 + bnq * 4;
            rb[i] = *(const float4*)&Bm[off];
            if (BSUM) {
                float4 e = *(const float4*)&Bm2[off];
                rb[i].x += e.x; rb[i].y += e.y; rb[i].z += e.z; rb[i].w += e.w;
            }
        }
    }

    for (int kt = 0; kt < NT; kt++) {
        const unsigned* Ac = As[kt & 1];
        const unsigned* Bc = Bs[kt & 1];
        #pragma unroll
        for (int ks = 0; ks < 2; ks++) {
            const int ko = ks * 8;
            const int x0 = (ko >> 2) << 3;
            const int x1 = x0 + 8;
            unsigned af[4][4], bf[4][2];
            #pragma unroll
            for (int mi = 0; mi < 4; mi++) {
                int mm = warpM * 64 + mi * 16;
                af[mi][0] = Ac[(ko + tig) * TFPAD + ((mm + gid) ^ x0)];
                af[mi][1] = Ac[(ko + tig) * TFPAD + ((mm + 8 + gid) ^ x0)];
                af[mi][2] = Ac[(ko + tig + 4) * TFPAD + ((mm + gid) ^ x1)];
                af[mi][3] = Ac[(ko + tig + 4) * TFPAD + ((mm + 8 + gid) ^ x1)];
            }
            #pragma unroll
            for (int ni = 0; ni < 4; ni++) {
                int nn = warpN * 32 + ni * 8;
                bf[ni][0] = Bc[(ko + tig) * TFPAD + nn + gid];
                bf[ni][1] = Bc[(ko + tig + 4) * TFPAD + nn + gid];
            }
            #pragma unroll
            for (int mi = 0; mi < 4; mi++)
                #pragma unroll
                for (int ni = 0; ni < 4; ni++)
                    MMA_TF32(acc[mi][ni], af[mi], bf[ni][0], bf[ni][1]);
        }
        if (kt + 1 < NT) {
            unsigned* An = As[(kt + 1) & 1];
            unsigned* Bn = Bs[(kt + 1) & 1];
            #pragma unroll
            for (int i = 0; i < 2; i++) {
                int mc = (am + i * 64) ^ axor;
                An[(akq * 4 + 0) * TFPAD + mc] = f2tf(ra[i].x);
                An[(akq * 4 + 1) * TFPAD + mc] = f2tf(ra[i].y);
                An[(akq * 4 + 2) * TFPAD + mc] = f2tf(ra[i].z);
                An[(akq * 4 + 3) * TFPAD + mc] = f2tf(ra[i].w);
                uint4 u; u.x = f2tf(rb[i].x); u.y = f2tf(rb[i].y); u.z = f2tf(rb[i].z); u.w = f2tf(rb[i].w);
                *(uint4*)&Bn[(bk + i * 8) * TFPAD + bnq * 4] = u;
            }
            if (kt + 2 < NT) {
                int k0 = (kt + 2) * 16;
                #pragma unroll
                for (int i = 0; i < 2; i++) {
                    ra[i] = *(const float4*)&A[(long)(m0 + am + i * 64) * lda + k0 + akq * 4];
                    long off = (long)(k0 + bk + i * 8) * ldb + n0 + bnq * 4;
                    rb[i] = *(const float4*)&Bm[off];
                    if (BSUM) {
                        float4 e = *(const float4*)&Bm2[off];
                        rb[i].x += e.x; rb[i].y += e.y; rb[i].z += e.z; rb[i].w += e.w;
                    }
                }
            }
        }
        __syncthreads();
    }

    #pragma unroll
    for (int mi = 0; mi < 4; mi++) {
        int r = m0 + warpM * 64 + mi * 16 + gid;
        #pragma unroll
        for (int ni = 0; ni < 4; ni++) {
            int cc = n0 + warpN * 32 + ni * 8 + tig * 2;
            float b0v = bias ? bias[cc] : 0.0f;
            float b1v = bias ? bias[cc + 1] : 0.0f;
            float2 v0, v1;
            if (COMBINE) {
                float a00 = 1.0f / (1.0f + __expf(-(acc[mi][ni][0] + b0v)));
                float a01 = 1.0f / (1.0f + __expf(-(acc[mi][ni][1] + b1v)));
                float a10 = 1.0f / (1.0f + __expf(-(acc[mi][ni][2] + b0v)));
                float a11 = 1.0f / (1.0f + __expf(-(acc[mi][ni][3] + b1v)));
                float2 lo0 = *(float2*)&g_lohtb[(long)r * 1024 + cc];
                float2 ht0 = *(float2*)&g_lohtb[(long)r * 1024 + 512 + cc];
                float2 lo1 = *(float2*)&g_lohtb[(long)(r + 8) * 1024 + cc];
                float2 ht1 = *(float2*)&g_lohtb[(long)(r + 8) * 1024 + 512 + cc];
                v0.x = lo0.x + ht0.x * a00; v0.y = lo0.y + ht0.y * a01;
                v1.x = lo1.x + ht1.x * a10; v1.y = lo1.y + ht1.y * a11;
            } else {
                v0.x = acc[mi][ni][0] + b0v; v0.y = acc[mi][ni][1] + b1v;
                v1.x = acc[mi][ni][2] + b0v; v1.y = acc[mi][ni][3] + b1v;
            }
            *(float2*)&C[(long)r * ldc + cc] = v0;
            *(float2*)&C[(long)(r + 8) * ldc + cc] = v1;
        }
    }
}

// ---------------- WIDE TF32 GEMM: 128x256x16, warp tile 64x64 --------------
constexpr int SMW_A = 16 * TFPAD;
constexpr int SMW_B = 16 * BWPAD;
constexpr int WSMEM_BYTES = (2 * SMW_A + 2 * SMW_B) * 4;   // 51200

__global__ void __launch_bounds__(256) tgemm_wide_k(
        const float* __restrict__ A, int lda,
        const float* __restrict__ Bm, int ldb,
        const float* __restrict__ bias,
        float* __restrict__ C, int ldc,
        int K) {
    extern __shared__ unsigned smw[];
    unsigned* As = smw;
    unsigned* Bs = smw + 2 * SMW_A;
    const int m0 = blockIdx.y * 128, n0 = blockIdx.x * 256;
    const int tid = threadIdx.x;
    const int lane = tid & 31, wid = tid >> 5;
    const int warpM = wid >> 2, warpN = wid & 3;
    const int gid = lane >> 2, tig = lane & 3;
    const int am = tid >> 2, akq = tid & 3;
    const int bk = tid >> 6, bnq = tid & 63;
    const int axor = akq * 8;

    float acc[4][8][4] = {};
    const int NT = K / 16;

    float4 ra[2], rb[4];
    #pragma unroll
    for (int i = 0; i < 2; i++)
        ra[i] = *(const float4*)&A[(long)(m0 + am + i * 64) * lda + akq * 4];
    #pragma unroll
    for (int i = 0; i < 4; i++)
        rb[i] = *(const float4*)&Bm[(long)(bk + i * 4) * ldb + n0 + bnq * 4];
    #pragma unroll
    for (int i = 0; i < 2; i++) {
        int mc = (am + i * 64) ^ axor;
        As[(akq * 4 + 0) * TFPAD + mc] = f2tf(ra[i].x);
        As[(akq * 4 + 1) * TFPAD + mc] = f2tf(ra[i].y);
        As[(akq * 4 + 2) * TFPAD + mc] = f2tf(ra[i].z);
        As[(akq * 4 + 3) * TFPAD + mc] = f2tf(ra[i].w);
    }
    #pragma unroll
    for (int i = 0; i < 4; i++) {
        uint4 u; u.x = f2tf(rb[i].x); u.y = f2tf(rb[i].y); u.z = f2tf(rb[i].z); u.w = f2tf(rb[i].w);
        *(uint4*)&Bs[(bk + i * 4) * BWPAD + bnq * 4] = u;
    }
    __syncthreads();
    if (NT > 1) {
        #pragma unroll
        for (int i = 0; i < 2; i++)
            ra[i] = *(const float4*)&A[(long)(m0 + am + i * 64) * lda + 16 + akq * 4];
        #pragma unroll
        for (int i = 0; i < 4; i++)
            rb[i] = *(const float4*)&Bm[(long)(16 + bk + i * 4) * ldb + n0 + bnq * 4];
    }

    for (int kt = 0; kt < NT; kt++) {
        const unsigned* Ac = As + (kt & 1) * SMW_A;
        const unsigned* Bc = Bs + (kt & 1) * SMW_B;
        #pragma unroll
        for (int ks = 0; ks < 2; ks++) {
            const int ko = ks * 8;
            const int x0 = (ko >> 2) << 3;
            const int x1 = x0 + 8;
            unsigned af[4][4], bf[8][2];
            #pragma unroll
            for (int mi = 0; mi < 4; mi++) {
                int mm = warpM * 64 + mi * 16;
                af[mi][0] = Ac[(ko + tig) * TFPAD + ((mm + gid) ^ x0)];
                af[mi][1] = Ac[(ko + tig) * TFPAD + ((mm + 8 + gid) ^ x0)];
                af[mi][2] = Ac[(ko + tig + 4) * TFPAD + ((mm + gid) ^ x1)];
                af[mi][3] = Ac[(ko + tig + 4) * TFPAD + ((mm + 8 + gid) ^ x1)];
            }
            #pragma unroll
            for (int ni = 0; ni < 8; ni++) {
                int nn = warpN * 64 + ni * 8;
                bf[ni][0] = Bc[(ko + tig) * BWPAD + nn + gid];
                bf[ni][1] = Bc[(ko + tig + 4) * BWPAD + nn + gid];
            }
            #pragma unroll
            for (int mi = 0; mi < 4; mi++)
                #pragma unroll
                for (int ni = 0; ni < 8; ni++)
                    MMA_TF32(acc[mi][ni], af[mi], bf[ni][0], bf[ni][1]);
        }
        if (kt + 1 < NT) {
            unsigned* An = As + ((kt + 1) & 1) * SMW_A;
            unsigned* Bn = Bs + ((kt + 1) & 1) * SMW_B;
            #pragma unroll
            for (int i = 0; i < 2; i++) {
                int mc = (am + i * 64) ^ axor;
                An[(akq * 4 + 0) * TFPAD + mc] = f2tf(ra[i].x);
                An[(akq * 4 + 1) * TFPAD + mc] = f2tf(ra[i].y);
                An[(akq * 4 + 2) * TFPAD + mc] = f2tf(ra[i].z);
                An[(akq * 4 + 3) * TFPAD + mc] = f2tf(ra[i].w);
            }
            #pragma unroll
            for (int i = 0; i < 4; i++) {
                uint4 u; u.x = f2tf(rb[i].x); u.y = f2tf(rb[i].y); u.z = f2tf(rb[i].z); u.w = f2tf(rb[i].w);
                *(uint4*)&Bn[(bk + i * 4) * BWPAD + bnq * 4] = u;
            }
            if (kt + 2 < NT) {
                int k0 = (kt + 2) * 16;
                #pragma unroll
                for (int i = 0; i < 2; i++)
                    ra[i] = *(const float4*)&A[(long)(m0 + am + i * 64) * lda + k0 + akq * 4];
                #pragma unroll
                for (int i = 0; i < 4; i++)
                    rb[i] = *(const float4*)&Bm[(long)(k0 + bk + i * 4) * ldb + n0 + bnq * 4];
            }
        }
        __syncthreads();
    }

    #pragma unroll
    for (int mi = 0; mi < 4; mi++) {
        int r = m0 + warpM * 64 + mi * 16 + gid;
        #pragma unroll
        for (int ni = 0; ni < 8; ni++) {
            int cc = n0 + warpN * 64 + ni * 8 + tig * 2;
            float b0v = bias ? bias[cc] : 0.0f;
            float b1v = bias ? bias[cc + 1] : 0.0f;
            float2 v0, v1;
            v0.x = acc[mi][ni][0] + b0v; v0.y = acc[mi][ni][1] + b1v;
            v1.x = acc[mi][ni][2] + b0v; v1.y = acc[mi][ni][3] + b1v;
            *(float2*)&C[(long)r * ldc + cc] = v0;
            *(float2*)&C[(long)(r + 8) * ldc + cc] = v1;
        }
    }
}

// ---------------- persistent LSTM (latency-diet barrier) -------------------
__device__ __forceinline__ int swz(int row, int s4) {
    return row * 128 + (s4 ^ ((row & 12) >> 1));
}
__device__ __forceinline__ float tanh_apx(float x) {
    float y;
    asm("tanh.approx.f32 %0, %1;" : "=f"(y) : "f"(x));
    return y;
}

__global__ void __launch_bounds__(256) lstm_persist_k(const int* __restrict__ xlen,
                                                      const float* __restrict__ W_hh,
                                                      float* __restrict__ oat, int wo) {
    extern __shared__ float sm[];
    float* ws  = sm;            // [16][512]  swizzled
    float* hs  = sm + 8192;     // [16][512]  swizzled
    float* red = sm + 16384;    // [256][16]  swizzled

    const int tid = threadIdx.x;
    const int k0  = blockIdx.x * 4;
    const int sc = tid >> 4, bt = (tid >> 2) & 3, jt = tid & 3;
    float4* ws4 = (float4*)ws;
    float4* hs4 = (float4*)hs;

    // load weight slice once (swizzled store)
    {
        int r = tid >> 4, c16 = tid & 15;
        int g = r >> 2, dk = r & 3;
        const float4* src = (const float4*)&W_hh[(long)(g * 512 + k0 + dk) * 512];
        #pragma unroll
        for (int i = 0; i < 8; i++) {
            int s4 = c16 + i * 16;
            ws4[swz(r, s4)] = src[s4];
        }
    }

    int ub = tid >> 2, udk = tid & 3;
    float creg = 0.0f; int xl = 0;
    if (tid < 64) {
        creg = g_cbuf[ub * 512 + k0 + udk];
        xl   = xlen[ub];
    }

    const int hxor = bt * 2;
    const int wxor = jt * 2;

    int* barp;
    asm("cvta.global.u64 %0, g_bar;" : "=l"(barp));

    for (int t = 0; t < Tt; t++) {
        // load h into swizzled smem (L2-coherent loads)
        const float4* hin = (const float4*)g_hbuf[t & 1];
        #pragma unroll
        for (int i = 0; i < 8; i++) {
            int j = tid + i * 256;
            int row = j >> 7, s4 = j & 127;
            hs4[swz(row, s4)] = __ldcg(&hin[j]);
        }
        float gxr[4];
        if (tid < 64) {
            #pragma unroll
            for (int g = 0; g < 4; g++)
                gxr[g] = g_Gx[(long)(ub * Tt + t) * G4H + g * 512 + k0 + udk];
        }
        __syncthreads();

        float acc[4][4] = {};
        #pragma unroll
        for (int i = 0; i < 8; i++) {
            int s4b = sc + (i << 4);
            float4 hv[4], wv[4];
            #pragma unroll
            for (int bi = 0; bi < 4; bi++)
                hv[bi] = hs4[(bt * 4 + bi) * 128 + (s4b ^ hxor)];
            #pragma unroll
            for (int ji = 0; ji < 4; ji++)
                wv[ji] = ws4[(jt * 4 + ji) * 128 + (s4b ^ wxor)];
            #pragma unroll
            for (int bi = 0; bi < 4; bi++)
                #pragma unroll
                for (int ji = 0; ji < 4; ji++)
                    acc[bi][ji] += hv[bi].x * wv[ji].x + hv[bi].y * wv[ji].y +
                                   hv[bi].z * wv[ji].z + hv[bi].w * wv[ji].w;
        }
        {
            int perm = bt * 4 + jt;
            #pragma unroll
            for (int bi = 0; bi < 4; bi++)
                #pragma unroll
                for (int ji = 0; ji < 4; ji++) {
                    int o = (bt * 4 + bi) * 16 + jt * 4 + ji;
                    red[o * 16 + (sc ^ perm)] = acc[bi][ji];
                }
        }
        __syncthreads();

        if (tid < 64) {
            int k = k0 + udk;
            float gate[4];
            #pragma unroll
            for (int g = 0; g < 4; g++) {
                int o = ub * 16 + g * 4 + udk;
                int perm = (o >> 6) * 4 + ((o >> 2) & 3);
                float s = 0.0f;
                #pragma unroll
                for (int scx = 0; scx < 16; scx++) s += red[o * 16 + (scx ^ perm)];
                gate[g] = gxr[g] + s;
            }
            float iv = 1.0f / (1.0f + __expf(-gate[0]));
            float fv = 1.0f / (1.0f + __expf(-gate[1]));
            float gg = tanh_apx(gate[2]);
            float ov = 1.0f / (1.0f + __expf(-gate[3]));
            float cn = fv * creg + iv * gg;
            float hn = ov * tanh_apx(cn);
            bool valid = (t < xl);
            creg = valid ? cn : creg;
            float hold = hs[swz(ub, k >> 2) * 4 + (k & 3)];
            float heff = valid ? hn : hold;
            __stcg(&g_hbuf[(t + 1) & 1][ub * 512 + k], heff);
            float lo = valid ? hn : 0.0f;
            long row = (long)(ub * Tt + t);
            g_lohtb[row * 1024 + k] = lo;
            g_attn_in[row * AIN + k] = lo;
            if (wo) oat[row * AIN + k] = lo;
        }
        __syncthreads();

        if (t + 1 < Tt) {
            // fence-elevated grid barrier: tid0 release-fences once, arrives,
            // acquire-spins on one L2 line (no nanosleep).
            if (tid == 0) {
                asm volatile("fence.acq_rel.gpu;" ::: "memory");
                atomicAdd(barp, 1);
                int target = 128 * (t + 1);
                int v;
                do {
                    asm volatile("ld.global.acquire.gpu.b32 %0, [%1];"
                                 : "=r"(v) : "l"(barp) : "memory");
                } while (v < target);
            }
            __syncthreads();
        }
    }
}

// ---------------- row softmax over S=512 -----------------------------------
__global__ void softmax_k() {
    __shared__ float red[8];
    float* p = g_att + (long)blockIdx.x * Ss;
    int tid = threadIdx.x;
    float m = -1e30f;
    for (int i = tid; i < Ss; i += 256) m = fmaxf(m, p[i]);
    #pragma unroll
    for (int o = 16; o; o >>= 1) m = fmaxf(m, __shfl_xor_sync(~0u, m, o));
    if ((tid & 31) == 0) red[tid >> 5] = m;
    __syncthreads();
    if (tid == 0) { float v = red[0]; for (int i = 1; i < 8; i++) v = fmaxf(v, red[i]); red[0] = v; }
    __syncthreads();
    m = red[0];
    __syncthreads();
    float s = 0.0f;
    for (int i = tid; i < Ss; i += 256) { float e = __expf(p[i] - m); p[i] = e; s += e; }
    #pragma unroll
    for (int o = 16; o; o >>= 1) s += __shfl_xor_sync(~0u, s, o);
    if ((tid & 31) == 0) red[tid >> 5] = s;
    __syncthreads();
    if (tid == 0) { float v = 0.0f; for (int i = 0; i < 8; i++) v += red[i]; red[0] = v; }
    __syncthreads();
    float inv = 1.0f / red[0];
    for (int i = tid; i < Ss; i += 256) p[i] *= inv;
}

// ---------------- host launcher --------------------------------------------
extern "C" void kernel_launch(void* const* d_in, const int* in_sizes, int n_in,
                              void* d_out, int out_size) {
    const int*   x       = (const int*)  d_in[0];
    const int*   xlen    = (const int*)  d_in[1];
    const float* h0      = (const float*)d_in[2];
    const float* c0      = (const float*)d_in[3];
    const float* eo      = (const float*)d_in[4];
    const float* emb     = (const float*)d_in[5];
    const float* W_att   = (const float*)d_in[6];
    const float* b_att   = (const float*)d_in[7];
    const float* W_ih    = (const float*)d_in[8];
    const float* W_hh    = (const float*)d_in[9];
    const float* b_ih    = (const float*)d_in[10];
    const float* b_hh    = (const float*)d_in[11];
    const float* W_align = (const float*)d_in[12];
    const float* b_align = (const float*)d_in[13];
    const float* W_out   = (const float*)d_in[14];
    const float* b_out   = (const float*)d_in[15];
    float* out = (float*)d_out;

    void *p_lin, *p_gx, *p_lohtb, *p_attn, *p_att, *p_op, *p_bsum, *p_wiht;
    cudaGetSymbolAddress(&p_lin,   g_lstm_in);
    cudaGetSymbolAddress(&p_gx,    g_Gx);
    cudaGetSymbolAddress(&p_lohtb, g_lohtb);
    cudaGetSymbolAddress(&p_attn,  g_attn_in);
    cudaGetSymbolAddress(&p_att,   g_att);
    cudaGetSymbolAddress(&p_op,    g_outpre);
    cudaGetSymbolAddress(&p_bsum,  g_bsum);
    cudaGetSymbolAddress(&p_wiht,  g_WihT);
    float* lin   = (float*)p_lin;   float* gx   = (float*)p_gx;
    float* lohtb = (float*)p_lohtb;
    float* attn  = (float*)p_attn;  float* att  = (float*)p_att;
    float* opre  = (float*)p_op;
    float* bsum  = (float*)p_bsum;  float* wihT = (float*)p_wiht;

    static bool attr_done = false;
    if (!attr_done) {
        cudaFuncSetAttribute(lstm_persist_k,
                             cudaFuncAttributeMaxDynamicSharedMemorySize, 84 * 1024);
        cudaFuncSetAttribute(tgemm_wide_k,
                             cudaFuncAttributeMaxDynamicSharedMemorySize, 64 * 1024);
        attr_done = true;
    }

    int wo = ((long)out_size >= OUT0 + OUT1) ? 1 : 0;
    int wt = ((long)out_size >= OUT0 + OUT1 + OUT2) ? 1 : 0;

    // (1) fused prep
    k_prep<<<(BT * KIN + 255) / 256, 256>>>(x, h0, c0, emb, b_ih, b_hh, out, wo, wt);

    // (2) W_ih transpose
    k_transpose_wih<<<dim3(KIN / 32, G4H / 32), dim3(32, 8)>>>(W_ih);

    // (3) Gx = lstm_input @ W_ih^T + (b_ih+b_hh)
    // ROUND 12: single-pass TF32 (was 3-pass error-compensated). The LSTM
    // recurrence is contractive (forget gate < 1), so the extra TF32 error
    // does not amplify; saves ~2/3 of this GEMM's time.
    tgemm_k<false, false><<<dim3(G4H / 128, BT / 128, 1), 256>>>(
        lin, KIN, 0, wihT, nullptr, G4H, 0, bsum, gx, G4H, 0, KIN);

    // (4) LSTM recurrence — persistent kernel (ncu capture slot)
    lstm_persist_k<<<128, 256, (8192 + 8192 + 4096) * sizeof(float)>>>(
        xlen, W_hh, out + OUT0, wo);

    // (5) att logits = attn_in @ W_att + b_att
    tgemm_k<false, false><<<dim3(Ss / 128, BT / 128, 1), 256>>>(
        attn, AIN, 0, W_att, nullptr, Ss, 0, b_att, att, Ss, 0, AIN);

    // (6) softmax rows
    softmax_k<<<BT, 256>>>();

    // (7) h_t_bar[b] = soft[b] @ (eo[b] + eo[b+dir])
    tgemm_k<true, false><<<dim3(Hh / 128, Tt / 128, Bb), 256>>>(
        att, Ss, (long)Tt * Ss,
        eo, eo + BSH, Hh, (long)Ss * Hh,
        nullptr,
        lohtb + Hh, 1024, (long)Tt * 1024,
        Ss);

    // (8) align GEMM with fused combine epilogue
    tgemm_k<false, true><<<dim3(Hh / 128, BT / 128, 1), 256>>>(
        lohtb, 1024, 0, W_align, nullptr, Hh, 0, b_align, opre, Hh, 0, 1024);

    // (9) out = out_pre @ W_out + b_out  — wide tile 128x256
    tgemm_wide_k<<<dim3(Vv / 256, BT / 128), 256, WSMEM_BYTES>>>(
        opre, Hh, W_out, Vv, b_out, out, Vv, Hh);
}

// round 16
// speedup vs baseline: 2.0400x; 1.2155x over previous
#include <cuda_runtime.h>
#include <cuda_fp16.h>
#include <math.h>

// Problem dims
#define Vv 32000
#define Ee 512
#define Hh 512
#define Bb 16
#define Tt 128
#define Ss 512

constexpr int BT   = Bb * Tt;          // 2048
constexpr int G4H  = 4 * Hh;           // 2048
constexpr int KIN  = Ee + Hh;          // 1024
constexpr int AIN  = 2 * Hh + Ee;      // 1536
constexpr long OUT0 = (long)BT * Vv;
constexpr long OUT1 = (long)BT * AIN;
constexpr long OUT2 = BT;
constexpr long BSH  = (long)Bb * Ss * Hh;

// ---------------- scratch (device globals) --------------------------------
__device__ float g_lstm_in[BT * KIN];
__device__ float g_Gx[BT * G4H];
__device__ float g_WihT[KIN * G4H];
__device__ float g_bsum[G4H];
__device__ float g_hbuf[2][Bb * Hh];
__device__ float g_cbuf[Bb * Hh];
__device__ float g_lohtb[BT * 1024];      // [ lstm_out | h_t_bar ]
__device__ float g_attn_in[BT * AIN];
__device__ float g_att[BT * Ss];
__device__ int   g_bar;
// fp16 k-paired operands for the output GEMM
__device__ unsigned g_Ap[BT * (Hh / 2)];             // out_pre  half2(k,k+1) [2048][256]
__device__ unsigned g_Wp[(long)(Hh / 2) * Vv];       // W_out    half2(k,k+1) [256][32000]

// ---------------- fused prep kernel ----------------------------------------
__global__ void k_prep(const int* __restrict__ x,
                       const float* __restrict__ h0,
                       const float* __restrict__ c0,
                       const float* __restrict__ emb,
                       const float* __restrict__ b_ih,
                       const float* __restrict__ b_hh,
                       float* __restrict__ out, int wo, int wt) {
    int i = blockIdx.x * 256 + threadIdx.x;
    if (i == 0) g_bar = 0;
    if (i < G4H) g_bsum[i] = b_ih[i] + b_hh[i];
    if (i < Bb * Hh) { g_hbuf[0][i] = h0[i]; g_cbuf[i] = c0[i]; }
    if (i < BT && wt) out[OUT0 + OUT1 + i] = (float)((Ss / Tt) * (i % Tt));
    if (i >= BT * KIN) return;
    int bt = i / KIN, c = i % KIN;
    int b = bt / Tt;
    float v;
    if (c < Hh) v = h0[b * Hh + c] + c0[b * Hh + c];
    else        v = emb[(long)x[bt] * Ee + (c - Hh)];
    g_lstm_in[i] = v;
    long ao = (long)bt * AIN + Hh + c;
    g_attn_in[ao] = v;
    if (wo) out[OUT0 + ao] = v;
}

// tiled transpose: W_ih [4H][KIN] -> g_WihT [KIN][4H]
__global__ void k_transpose_wih(const float* __restrict__ W) {
    __shared__ float tile[32][33];
    int bx = blockIdx.x * 32, by = blockIdx.y * 32;
    int x = bx + threadIdx.x;
    #pragma unroll
    for (int i = 0; i < 32; i += 8)
        tile[threadIdx.y + i][threadIdx.x] = W[(long)(by + threadIdx.y + i) * KIN + x];
    __syncthreads();
    int xo = by + threadIdx.x;
    #pragma unroll
    for (int i = 0; i < 32; i += 8)
        g_WihT[(long)(bx + threadIdx.y + i) * G4H + xo] = tile[threadIdx.x][threadIdx.y + i];
}

// pack W_out [512][32000] fp32 -> g_Wp [256][32000] half2 (k-pairs)
__global__ void k_pack_wout(const float* __restrict__ W) {
    long i = (long)blockIdx.x * 256 + threadIdx.x;   // over 256*8000 float4-groups
    if (i >= 256L * 8000) return;
    int k2 = (int)(i / 8000), c = (int)(i % 8000);
    const float4 r0 = *(const float4*)&W[(long)(2 * k2) * Vv + c * 4];
    const float4 r1 = *(const float4*)&W[(long)(2 * k2 + 1) * Vv + c * 4];
    uint4 u;
    __half2 h;
    h = __floats2half2_rn(r0.x, r1.x); u.x = *(unsigned*)&h;
    h = __floats2half2_rn(r0.y, r1.y); u.y = *(unsigned*)&h;
    h = __floats2half2_rn(r0.z, r1.z); u.z = *(unsigned*)&h;
    h = __floats2half2_rn(r0.w, r1.w); u.w = *(unsigned*)&h;
    *(uint4*)&g_Wp[i * 4] = u;
}

// ---------------- TF32 helpers --------------------------------------------
__device__ __forceinline__ unsigned f2tf(float f) {
    unsigned u;
    asm("cvt.rna.tf32.f32 %0, %1;" : "=r"(u) : "f"(f));
    return u;
}
#define TFPAD 136

#define MMA_TF32(ACC, AF, B0, B1)                                              \
    asm volatile(                                                              \
        "mma.sync.aligned.m16n8k8.row.col.f32.tf32.tf32.f32 "                  \
        "{%0,%1,%2,%3}, {%4,%5,%6,%7}, {%8,%9}, {%0,%1,%2,%3};"                \
        : "+f"((ACC)[0]), "+f"((ACC)[1]), "+f"((ACC)[2]), "+f"((ACC)[3])       \
        : "r"((AF)[0]), "r"((AF)[1]), "r"((AF)[2]), "r"((AF)[3]),              \
          "r"(B0), "r"(B1))

#define MMA_F16(ACC, AF, B0, B1)                                               \
    asm volatile(                                                              \
        "mma.sync.aligned.m16n8k16.row.col.f32.f16.f16.f32 "                   \
        "{%0,%1,%2,%3}, {%4,%5,%6,%7}, {%8,%9}, {%0,%1,%2,%3};"                \
        : "+f"((ACC)[0]), "+f"((ACC)[1]), "+f"((ACC)[2]), "+f"((ACC)[3])       \
        : "r"((AF)[0]), "r"((AF)[1]), "r"((AF)[2]), "r"((AF)[3]),              \
          "r"(B0), "r"(B1))

// ---------------- TF32 GEMM, 128x128x16, double-buffered smem -------------
// BSUM: B tile = Bm + Bm2.  COMBINE: epilogue computes out_pre =
// lo + htb*sigmoid(acc+bias) and writes half2 k-pairs into g_Ap.
template<bool BSUM, bool COMBINE>
__global__ void __launch_bounds__(256) tgemm_k(
        const float* __restrict__ A, int lda, long sA,
        const float* __restrict__ Bm, const float* __restrict__ Bm2,
        int ldb, long sB,
        const float* __restrict__ bias,
        float* __restrict__ C, int ldc, long sC,
        int K) {
    __shared__ unsigned As[2][16 * TFPAD];
    __shared__ unsigned Bs[2][16 * TFPAD];
    long z = blockIdx.z;
    A += z * sA; Bm += z * sB; if (BSUM) Bm2 += z * sB; C += z * sC;
    const int m0 = blockIdx.y * 128, n0 = blockIdx.x * 128;
    const int tid = threadIdx.x;
    const int lane = tid & 31, wid = tid >> 5;
    const int warpM = wid >> 2, warpN = wid & 3;
    const int gid = lane >> 2, tig = lane & 3;
    const int am = tid >> 2, akq = tid & 3;
    const int bk = tid >> 5, bnq = tid & 31;
    const int axor = akq * 8;

    float acc[4][4][4] = {};
    const int NT = K / 16;

    float4 ra[2], rb[2];
    #pragma unroll
    for (int i = 0; i < 2; i++) {
        ra[i] = *(const float4*)&A[(long)(m0 + am + i * 64) * lda + akq * 4];
        long off = (long)(bk + i * 8) * ldb + n0 + bnq * 4;
        rb[i] = *(const float4*)&Bm[off];
        if (BSUM) {
            float4 e = *(const float4*)&Bm2[off];
            rb[i].x += e.x; rb[i].y += e.y; rb[i].z += e.z; rb[i].w += e.w;
        }
    }
    #pragma unroll
    for (int i = 0; i < 2; i++) {
        int mc = (am + i * 64) ^ axor;
        As[0][(akq * 4 + 0) * TFPAD + mc] = f2tf(ra[i].x);
        As[0][(akq * 4 + 1) * TFPAD + mc] = f2tf(ra[i].y);
        As[0][(akq * 4 + 2) * TFPAD + mc] = f2tf(ra[i].z);
        As[0][(akq * 4 + 3) * TFPAD + mc] = f2tf(ra[i].w);
        uint4 u; u.x = f2tf(rb[i].x); u.y = f2tf(rb[i].y); u.z = f2tf(rb[i].z); u.w = f2tf(rb[i].w);
        *(uint4*)&Bs[0][(bk + i * 8) * TFPAD + bnq * 4] = u;
    }
    __syncthreads();
    if (NT > 1) {
        #pragma unroll
        for (int i = 0; i < 2; i++) {
            ra[i] = *(const float4*)&A[(long)(m0 + am + i * 64) * lda + 16 + akq * 4];
            long off = (long)(16 + bk + i * 8) * ldb + n0 + bnq * 4;
            rb[i] = *(const float4*)&Bm[off];
            if (BSUM) {
                float4 e = *(const float4*)&Bm2[off];
                rb[i].x += e.x; rb[i].y += e.y; rb[i].z += e.z; rb[i].w += e.w;
            }
        }
    }

    for (int kt = 0; kt < NT; kt++) {
        const unsigned* Ac = As[kt & 1];
        const unsigned* Bc = Bs[kt & 1];
        #pragma unroll
        for (int ks = 0; ks < 2; ks++) {
            const int ko = ks * 8;
            const int x0 = (ko >> 2) << 3;
            const int x1 = x0 + 8;
            unsigned af[4][4], bf[4][2];
            #pragma unroll
            for (int mi = 0; mi < 4; mi++) {
                int mm = warpM * 64 + mi * 16;
                af[mi][0] = Ac[(ko + tig) * TFPAD + ((mm + gid) ^ x0)];
                af[mi][1] = Ac[(ko + tig) * TFPAD + ((mm + 8 + gid) ^ x0)];
                af[mi][2] = Ac[(ko + tig + 4) * TFPAD + ((mm + gid) ^ x1)];
                af[mi][3] = Ac[(ko + tig + 4) * TFPAD + ((mm + 8 + gid) ^ x1)];
            }
            #pragma unroll
            for (int ni = 0; ni < 4; ni++) {
                int nn = warpN * 32 + ni * 8;
                bf[ni][0] = Bc[(ko + tig) * TFPAD + nn + gid];
                bf[ni][1] = Bc[(ko + tig + 4) * TFPAD + nn + gid];
            }
            #pragma unroll
            for (int mi = 0; mi < 4; mi++)
                #pragma unroll
                for (int ni = 0; ni < 4; ni++)
                    MMA_TF32(acc[mi][ni], af[mi], bf[ni][0], bf[ni][1]);
        }
        if (kt + 1 < NT) {
            unsigned* An = As[(kt + 1) & 1];
            unsigned* Bn = Bs[(kt + 1) & 1];
            #pragma unroll
            for (int i = 0; i < 2; i++) {
                int mc = (am + i * 64) ^ axor;
                An[(akq * 4 + 0) * TFPAD + mc] = f2tf(ra[i].x);
                An[(akq * 4 + 1) * TFPAD + mc] = f2tf(ra[i].y);
                An[(akq * 4 + 2) * TFPAD + mc] = f2tf(ra[i].z);
                An[(akq * 4 + 3) * TFPAD + mc] = f2tf(ra[i].w);
                uint4 u; u.x = f2tf(rb[i].x); u.y = f2tf(rb[i].y); u.z = f2tf(rb[i].z); u.w = f2tf(rb[i].w);
                *(uint4*)&Bn[(bk + i * 8) * TFPAD + bnq * 4] = u;
            }
            if (kt + 2 < NT) {
                int k0 = (kt + 2) * 16;
                #pragma unroll
                for (int i = 0; i < 2; i++) {
                    ra[i] = *(const float4*)&A[(long)(m0 + am + i * 64) * lda + k0 + akq * 4];
                    long off = (long)(k0 + bk + i * 8) * ldb + n0 + bnq * 4;
                    rb[i] = *(const float4*)&Bm[off];
                    if (BSUM) {
                        float4 e = *(const float4*)&Bm2[off];
                        rb[i].x += e.x; rb[i].y += e.y; rb[i].z += e.z; rb[i].w += e.w;
                    }
                }
            }
        }
        __syncthreads();
    }

    #pragma unroll
    for (int mi = 0; mi < 4; mi++) {
        int r = m0 + warpM * 64 + mi * 16 + gid;
        #pragma unroll
        for (int ni = 0; ni < 4; ni++) {
            int cc = n0 + warpN * 32 + ni * 8 + tig * 2;
            float b0v = bias ? bias[cc] : 0.0f;
            float b1v = bias ? bias[cc + 1] : 0.0f;
            if (COMBINE) {
                float vv[2][2];
                float a00 = 1.0f / (1.0f + __expf(-(acc[mi][ni][0] + b0v)));
                float a01 = 1.0f / (1.0f + __expf(-(acc[mi][ni][1] + b1v)));
                float a10 = 1.0f / (1.0f + __expf(-(acc[mi][ni][2] + b0v)));
                float a11 = 1.0f / (1.0f + __expf(-(acc[mi][ni][3] + b1v)));
                float2 lo0 = *(float2*)&g_lohtb[(long)r * 1024 + cc];
                float2 ht0 = *(float2*)&g_lohtb[(long)r * 1024 + 512 + cc];
                float2 lo1 = *(float2*)&g_lohtb[(long)(r + 8) * 1024 + cc];
                float2 ht1 = *(float2*)&g_lohtb[(long)(r + 8) * 1024 + 512 + cc];
                vv[0][0] = lo0.x + ht0.x * a00; vv[0][1] = lo0.y + ht0.y * a01;
                vv[1][0] = lo1.x + ht1.x * a10; vv[1][1] = lo1.y + ht1.y * a11;
                #pragma unroll
                for (int q = 0; q < 2; q++) {
                    __half2 h = __floats2half2_rn(vv[q][0], vv[q][1]);
                    g_Ap[(long)(r + q * 8) * (Hh / 2) + (cc >> 1)] = *(unsigned*)&h;
                }
            } else {
                float2 v0, v1;
                v0.x = acc[mi][ni][0] + b0v; v0.y = acc[mi][ni][1] + b1v;
                v1.x = acc[mi][ni][2] + b0v; v1.y = acc[mi][ni][3] + b1v;
                *(float2*)&C[(long)r * ldc + cc] = v0;
                *(float2*)&C[(long)(r + 8) * ldc + cc] = v1;
            }
        }
    }
}

// ---------------- fp16 WIDE GEMM: 128x256, k-tile 32, m16n8k16 -------------
// out = out_pre @ W_out + b_out, both operands pre-packed as half2 k-pairs.
constexpr int HAPAD = 20;      // b32 per A m-row   (16 data + 4 pad)
constexpr int HBPAD = 264;     // b32 per B k2-row  (256 data + 8 pad)
constexpr int HSM_A = 128 * HAPAD;   // 2560 b32 per buffer
constexpr int HSM_B = 16 * HBPAD;    // 4224 b32 per buffer
constexpr int HSMEM_BYTES = (2 * HSM_A + 2 * HSM_B) * 4;   // 54272

__global__ void __launch_bounds__(256) tgemm_wide_h_k(
        const float* __restrict__ bias, float* __restrict__ C) {
    extern __shared__ unsigned smh[];
    unsigned* As = smh;                  // [2][HSM_A]
    unsigned* Bs = smh + 2 * HSM_A;      // [2][HSM_B]
    const int m0 = blockIdx.y * 128, n0 = blockIdx.x * 256;
    const int tid = threadIdx.x;
    const int lane = tid & 31, wid = tid >> 5;
    const int warpM = wid >> 2, warpN = wid & 3;
    const int gid = lane >> 2, tig = lane & 3;
    // gmem load coords
    const int ar = tid >> 2, aq = tid & 3;     // A: rows ar, ar+64; quarter aq
    const int br = tid >> 6, bc = tid & 63;    // B: rows br+{0,4,8,12}; col grp bc

    const uint4* gA = (const uint4*)g_Ap;      // row = 64 uint4
    const uint4* gB = (const uint4*)g_Wp;      // row = 8000 uint4

    float acc[4][8][4] = {};
    const int NT = Hh / 32;                    // 16

    uint4 ra[2], rb[4];
    #pragma unroll
    for (int i = 0; i < 2; i++)
        ra[i] = gA[(long)(m0 + ar + i * 64) * 64 + aq];
    #pragma unroll
    for (int i = 0; i < 4; i++)
        rb[i] = gB[(long)(br + i * 4) * 8000 + (n0 >> 2) + bc];
    #pragma unroll
    for (int i = 0; i < 2; i++)
        *(uint4*)&As[(ar + i * 64) * HAPAD + aq * 4] = ra[i];
    #pragma unroll
    for (int i = 0; i < 4; i++)
        *(uint4*)&Bs[(br + i * 4) * HBPAD + bc * 4] = rb[i];
    __syncthreads();
    #pragma unroll
    for (int i = 0; i < 2; i++)
        ra[i] = gA[(long)(m0 + ar + i * 64) * 64 + 4 + aq];
    #pragma unroll
    for (int i = 0; i < 4; i++)
        rb[i] = gB[(long)(16 + br + i * 4) * 8000 + (n0 >> 2) + bc];

    for (int kt = 0; kt < NT; kt++) {
        const unsigned* Ac = As + (kt & 1) * HSM_A;
        const unsigned* Bc = Bs + (kt & 1) * HSM_B;
        #pragma unroll
        for (int ks = 0; ks < 2; ks++) {
            const int k2o = ks * 8;
            unsigned af[4][4], bf[8][2];
            #pragma unroll
            for (int mi = 0; mi < 4; mi++) {
                int mm = warpM * 64 + mi * 16;
                af[mi][0] = Ac[(mm + gid) * HAPAD + k2o + tig];
                af[mi][1] = Ac[(mm + 8 + gid) * HAPAD + k2o + tig];
                af[mi][2] = Ac[(mm + gid) * HAPAD + k2o + 4 + tig];
                af[mi][3] = Ac[(mm + 8 + gid) * HAPAD + k2o + 4 + tig];
            }
            #pragma unroll
            for (int ni = 0; ni < 8; ni++) {
                int nn = warpN * 64 + ni * 8;
                bf[ni][0] = Bc[(k2o + tig) * HBPAD + nn + gid];
                bf[ni][1] = Bc[(k2o + 4 + tig) * HBPAD + nn + gid];
            }
            #pragma unroll
            for (int mi = 0; mi < 4; mi++)
                #pragma unroll
                for (int ni = 0; ni < 8; ni++)
                    MMA_F16(acc[mi][ni], af[mi], bf[ni][0], bf[ni][1]);
        }
        if (kt + 1 < NT) {
            unsigned* An = As + ((kt + 1) & 1) * HSM_A;
            unsigned* Bn = Bs + ((kt + 1) & 1) * HSM_B;
            #pragma unroll
            for (int i = 0; i < 2; i++)
                *(uint4*)&An[(ar + i * 64) * HAPAD + aq * 4] = ra[i];
            #pragma unroll
            for (int i = 0; i < 4; i++)
                *(uint4*)&Bn[(br + i * 4) * HBPAD + bc * 4] = rb[i];
            if (kt + 2 < NT) {
                int k40 = (kt + 2) * 4;          // uint4 offset per A row
                int k20 = (kt + 2) * 16;         // k2 row base for B
                #pragma unroll
                for (int i = 0; i < 2; i++)
                    ra[i] = gA[(long)(m0 + ar + i * 64) * 64 + k40 + aq];
                #pragma unroll
                for (int i = 0; i < 4; i++)
                    rb[i] = gB[(long)(k20 + br + i * 4) * 8000 + (n0 >> 2) + bc];
            }
        }
        __syncthreads();
    }

    #pragma unroll
    for (int mi = 0; mi < 4; mi++) {
        int r = m0 + warpM * 64 + mi * 16 + gid;
        #pragma unroll
        for (int ni = 0; ni < 8; ni++) {
            int cc = n0 + warpN * 64 + ni * 8 + tig * 2;
            float b0v = bias[cc], b1v = bias[cc + 1];
            float2 v0, v1;
            v0.x = acc[mi][ni][0] + b0v; v0.y = acc[mi][ni][1] + b1v;
            v1.x = acc[mi][ni][2] + b0v; v1.y = acc[mi][ni][3] + b1v;
            *(float2*)&C[(long)r * Vv + cc] = v0;
            *(float2*)&C[(long)(r + 8) * Vv + cc] = v1;
        }
    }
}

// ---------------- persistent LSTM (latency-diet barrier) -------------------
__device__ __forceinline__ int swz(int row, int s4) {
    return row * 128 + (s4 ^ ((row & 12) >> 1));
}
__device__ __forceinline__ float tanh_apx(float x) {
    float y;
    asm("tanh.approx.f32 %0, %1;" : "=f"(y) : "f"(x));
    return y;
}

__global__ void __launch_bounds__(256) lstm_persist_k(const int* __restrict__ xlen,
                                                      const float* __restrict__ W_hh,
                                                      float* __restrict__ oat, int wo) {
    extern __shared__ float sm[];
    float* ws  = sm;
    float* hs  = sm + 8192;
    float* red = sm + 16384;

    const int tid = threadIdx.x;
    const int k0  = blockIdx.x * 4;
    const int sc = tid >> 4, bt = (tid >> 2) & 3, jt = tid & 3;
    float4* ws4 = (float4*)ws;
    float4* hs4 = (float4*)hs;

    {
        int r = tid >> 4, c16 = tid & 15;
        int g = r >> 2, dk = r & 3;
        const float4* src = (const float4*)&W_hh[(long)(g * 512 + k0 + dk) * 512];
        #pragma unroll
        for (int i = 0; i < 8; i++) {
            int s4 = c16 + i * 16;
            ws4[swz(r, s4)] = src[s4];
        }
    }

    int ub = tid >> 2, udk = tid & 3;
    float creg = 0.0f; int xl = 0;
    if (tid < 64) {
        creg = g_cbuf[ub * 512 + k0 + udk];
        xl   = xlen[ub];
    }

    const int hxor = bt * 2;
    const int wxor = jt * 2;

    int* barp;
    asm("cvta.global.u64 %0, g_bar;" : "=l"(barp));

    for (int t = 0; t < Tt; t++) {
        const float4* hin = (const float4*)g_hbuf[t & 1];
        #pragma unroll
        for (int i = 0; i < 8; i++) {
            int j = tid + i * 256;
            int row = j >> 7, s4 = j & 127;
            hs4[swz(row, s4)] = __ldcg(&hin[j]);
        }
        float gxr[4];
        if (tid < 64) {
            #pragma unroll
            for (int g = 0; g < 4; g++)
                gxr[g] = g_Gx[(long)(ub * Tt + t) * G4H + g * 512 + k0 + udk];
        }
        __syncthreads();

        float acc[4][4] = {};
        #pragma unroll
        for (int i = 0; i < 8; i++) {
            int s4b = sc + (i << 4);
            float4 hv[4], wv[4];
            #pragma unroll
            for (int bi = 0; bi < 4; bi++)
                hv[bi] = hs4[(bt * 4 + bi) * 128 + (s4b ^ hxor)];
            #pragma unroll
            for (int ji = 0; ji < 4; ji++)
                wv[ji] = ws4[(jt * 4 + ji) * 128 + (s4b ^ wxor)];
            #pragma unroll
            for (int bi = 0; bi < 4; bi++)
                #pragma unroll
                for (int ji = 0; ji < 4; ji++)
                    acc[bi][ji] += hv[bi].x * wv[ji].x + hv[bi].y * wv[ji].y +
                                   hv[bi].z * wv[ji].z + hv[bi].w * wv[ji].w;
        }
        {
            int perm = bt * 4 + jt;
            #pragma unroll
            for (int bi = 0; bi < 4; bi++)
                #pragma unroll
                for (int ji = 0; ji < 4; ji++) {
                    int o = (bt * 4 + bi) * 16 + jt * 4 + ji;
                    red[o * 16 + (sc ^ perm)] = acc[bi][ji];
                }
        }
        __syncthreads();

        if (tid < 64) {
            int k = k0 + udk;
            float gate[4];
            #pragma unroll
            for (int g = 0; g < 4; g++) {
                int o = ub * 16 + g * 4 + udk;
                int perm = (o >> 6) * 4 + ((o >> 2) & 3);
                float s = 0.0f;
                #pragma unroll
                for (int scx = 0; scx < 16; scx++) s += red[o * 16 + (scx ^ perm)];
                gate[g] = gxr[g] + s;
            }
            float iv = 1.0f / (1.0f + __expf(-gate[0]));
            float fv = 1.0f / (1.0f + __expf(-gate[1]));
            float gg = tanh_apx(gate[2]);
            float ov = 1.0f / (1.0f + __expf(-gate[3]));
            float cn = fv * creg + iv * gg;
            float hn = ov * tanh_apx(cn);
            bool valid = (t < xl);
            creg = valid ? cn : creg;
            float hold = hs[swz(ub, k >> 2) * 4 + (k & 3)];
            float heff = valid ? hn : hold;
            __stcg(&g_hbuf[(t + 1) & 1][ub * 512 + k], heff);
            float lo = valid ? hn : 0.0f;
            long row = (long)(ub * Tt + t);
            g_lohtb[row * 1024 + k] = lo;
            g_attn_in[row * AIN + k] = lo;
            if (wo) oat[row * AIN + k] = lo;
        }
        __syncthreads();

        if (t + 1 < Tt) {
            if (tid == 0) {
                asm volatile("fence.acq_rel.gpu;" ::: "memory");
                atomicAdd(barp, 1);
                int target = 128 * (t + 1);
                int v;
                do {
                    asm volatile("ld.global.acquire.gpu.b32 %0, [%1];"
                                 : "=r"(v) : "l"(barp) : "memory");
                } while (v < target);
            }
            __syncthreads();
        }
    }
}

// ---------------- row softmax over S=512 -----------------------------------
__global__ void softmax_k() {
    __shared__ float red[8];
    float* p = g_att + (long)blockIdx.x * Ss;
    int tid = threadIdx.x;
    float m = -1e30f;
    for (int i = tid; i < Ss; i += 256) m = fmaxf(m, p[i]);
    #pragma unroll
    for (int o = 16; o; o >>= 1) m = fmaxf(m, __shfl_xor_sync(~0u, m, o));
    if ((tid & 31) == 0) red[tid >> 5] = m;
    __syncthreads();
    if (tid == 0) { float v = red[0]; for (int i = 1; i < 8; i++) v = fmaxf(v, red[i]); red[0] = v; }
    __syncthreads();
    m = red[0];
    __syncthreads();
    float s = 0.0f;
    for (int i = tid; i < Ss; i += 256) { float e = __expf(p[i] - m); p[i] = e; s += e; }
    #pragma unroll
    for (int o = 16; o; o >>= 1) s += __shfl_xor_sync(~0u, s, o);
    if ((tid & 31) == 0) red[tid >> 5] = s;
    __syncthreads();
    if (tid == 0) { float v = 0.0f; for (int i = 0; i < 8; i++) v += red[i]; red[0] = v; }
    __syncthreads();
    float inv = 1.0f / red[0];
    for (int i = tid; i < Ss; i += 256) p[i] *= inv;
}

// ---------------- host launcher --------------------------------------------
extern "C" void kernel_launch(void* const* d_in, const int* in_sizes, int n_in,
                              void* d_out, int out_size) {
    const int*   x       = (const int*)  d_in[0];
    const int*   xlen    = (const int*)  d_in[1];
    const float* h0      = (const float*)d_in[2];
    const float* c0      = (const float*)d_in[3];
    const float* eo      = (const float*)d_in[4];
    const float* emb     = (const float*)d_in[5];
    const float* W_att   = (const float*)d_in[6];
    const float* b_att   = (const float*)d_in[7];
    const float* W_ih    = (const float*)d_in[8];
    const float* W_hh    = (const float*)d_in[9];
    const float* b_ih    = (const float*)d_in[10];
    const float* b_hh    = (const float*)d_in[11];
    const float* W_align = (const float*)d_in[12];
    const float* b_align = (const float*)d_in[13];
    const float* W_out   = (const float*)d_in[14];
    const float* b_out   = (const float*)d_in[15];
    float* out = (float*)d_out;

    void *p_lin, *p_gx, *p_lohtb, *p_attn, *p_att, *p_bsum, *p_wiht;
    cudaGetSymbolAddress(&p_lin,   g_lstm_in);
    cudaGetSymbolAddress(&p_gx,    g_Gx);
    cudaGetSymbolAddress(&p_lohtb, g_lohtb);
    cudaGetSymbolAddress(&p_attn,  g_attn_in);
    cudaGetSymbolAddress(&p_att,   g_att);
    cudaGetSymbolAddress(&p_bsum,  g_bsum);
    cudaGetSymbolAddress(&p_wiht,  g_WihT);
    float* lin   = (float*)p_lin;   float* gx   = (float*)p_gx;
    float* lohtb = (float*)p_lohtb;
    float* attn  = (float*)p_attn;  float* att  = (float*)p_att;
    float* bsum  = (float*)p_bsum;  float* wihT = (float*)p_wiht;

    static bool attr_done = false;
    if (!attr_done) {
        cudaFuncSetAttribute(lstm_persist_k,
                             cudaFuncAttributeMaxDynamicSharedMemorySize, 84 * 1024);
        cudaFuncSetAttribute(tgemm_wide_h_k,
                             cudaFuncAttributeMaxDynamicSharedMemorySize, HSMEM_BYTES);
        attr_done = true;
    }

    int wo = ((long)out_size >= OUT0 + OUT1) ? 1 : 0;
    int wt = ((long)out_size >= OUT0 + OUT1 + OUT2) ? 1 : 0;

    // (1) fused prep
    k_prep<<<(BT * KIN + 255) / 256, 256>>>(x, h0, c0, emb, b_ih, b_hh, out, wo, wt);

    // (2) W_out -> half2 k-pair pack (independent; runs early)
    k_pack_wout<<<(int)((256L * 8000 + 255) / 256), 256>>>(W_out);

    // (3) W_ih transpose
    k_transpose_wih<<<dim3(KIN / 32, G4H / 32), dim3(32, 8)>>>(W_ih);

    // (4) Gx = lstm_input @ W_ih^T + (b_ih+b_hh)  — 1-pass tf32
    tgemm_k<false, false><<<dim3(G4H / 128, BT / 128, 1), 256>>>(
        lin, KIN, 0, wihT, nullptr, G4H, 0, bsum, gx, G4H, 0, KIN);

    // (5) LSTM recurrence — persistent kernel
    lstm_persist_k<<<128, 256, (8192 + 8192 + 4096) * sizeof(float)>>>(
        xlen, W_hh, out + OUT0, wo);

    // (6) att logits = attn_in @ W_att + b_att
    tgemm_k<false, false><<<dim3(Ss / 128, BT / 128, 1), 256>>>(
        attn, AIN, 0, W_att, nullptr, Ss, 0, b_att, att, Ss, 0, AIN);

    // (7) softmax rows
    softmax_k<<<BT, 256>>>();

    // (8) h_t_bar[b] = soft[b] @ (eo[b] + eo[b+dir])
    tgemm_k<true, false><<<dim3(Hh / 128, Tt / 128, Bb), 256>>>(
        att, Ss, (long)Tt * Ss,
        eo, eo + BSH, Hh, (long)Ss * Hh,
        nullptr,
        lohtb + Hh, 1024, (long)Tt * 1024,
        Ss);

    // (9) align GEMM; COMBINE epilogue emits out_pre as half2 k-pairs
    tgemm_k<false, true><<<dim3(Hh / 128, BT / 128, 1), 256>>>(
        lohtb, 1024, 0, W_align, nullptr, Hh, 0, b_align, out, Hh, 0, 1024);

    // (10) out = out_pre @ W_out + b_out  — fp16 m16n8k16 wide GEMM
    tgemm_wide_h_k<<<dim3(Vv / 256, BT / 128), 256, HSMEM_BYTES>>>(b_out, out);
}